// round 11
// baseline (speedup 1.0000x reference)
#include <cuda_runtime.h>
#include <math.h>
#include <stdint.h>

// Problem-size maxima (fixed by the dataset: N=100000, E=1600000, F=H=128, OUT=40)
#define NMAX 100000
#define EMAX 1600000
#define FDIM 128
#define SCAN_BS 2048
#define NCHUNK 4

// ---------------- scratch (static device globals; no allocation) ----------------
__device__ __align__(16) float g_bufG [(size_t)NMAX * FDIM];  // h1 = x@W1
__device__ __align__(16) float g_bufG2[(size_t)NMAX * FDIM];  // h2 = out1@W2 (separate! avoids race)
__device__ __align__(16) float g_bufO [(size_t)NMAX * FDIM];  // out1, then s = out2+out1
__device__ float g_dinv[NMAX];
__device__ __align__(16) int g_cnt[NMAX + 8];
__device__ __align__(16) int g_rowstart[NMAX + 8];
__device__ __align__(16) int g_cursor[NMAX + 8];
__device__ int   g_csrc[EMAX];
__device__ int   g_bsum[64];
__device__ int   g_boff[64];

// ---------------- packed fp32x2 helpers ----------------
__device__ __forceinline__ unsigned long long pack2_dup(float x) {
    unsigned long long r;
    asm("mov.b64 %0, {%1, %1};" : "=l"(r) : "f"(x));
    return r;
}
__device__ __forceinline__ void fma2(unsigned long long& d,
                                     unsigned long long a,
                                     unsigned long long b) {
    asm("fma.rn.f32x2 %0, %1, %2, %0;" : "+l"(d) : "l"(a), "l"(b));
}

// ---------------- CSR build ----------------
__global__ void zero_cnt_kernel(int n) {
    int i = blockIdx.x * blockDim.x + threadIdx.x;
    if (i < n + 8) g_cnt[i] = 0;
}

__global__ void count_kernel(const int* __restrict__ dst, int e) {
    int i = blockIdx.x * blockDim.x + threadIdx.x;
    if (i < e) atomicAdd(&g_cnt[dst[i]], 1);
}

__global__ __launch_bounds__(256) void scan1_kernel(int n) {
    __shared__ int red[256];
    int b = blockIdx.x, t = threadIdx.x;
    int base = b * SCAN_BS + t * 8;
    int s = 0;
    if (base + 8 <= n) {
        int4 a = *(const int4*)&g_cnt[base];
        int4 c = *(const int4*)&g_cnt[base + 4];
        s = a.x + a.y + a.z + a.w + c.x + c.y + c.z + c.w;
    } else {
        for (int i = 0; i < 8; i++) {
            int idx = base + i;
            if (idx < n) s += g_cnt[idx];
        }
    }
    red[t] = s;
    __syncthreads();
    for (int off = 128; off > 0; off >>= 1) {
        if (t < off) red[t] += red[t + off];
        __syncthreads();
    }
    if (t == 0) g_bsum[b] = red[0];
}

__global__ void scan2_kernel(int nb, int n, int e_total) {
    if (threadIdx.x == 0 && blockIdx.x == 0) {
        int acc = 0;
        for (int i = 0; i < nb; i++) {
            g_boff[i] = acc;
            acc += g_bsum[i];
        }
        g_rowstart[n] = e_total;
    }
}

__global__ __launch_bounds__(256) void scan3_kernel(int n) {
    __shared__ int sh[256];
    int b = blockIdx.x, t = threadIdx.x;
    int base = b * SCAN_BS + t * 8;
    int loc[8];
    int s = 0;
    if (base + 8 <= n) {
        int4 a = *(const int4*)&g_cnt[base];
        int4 c = *(const int4*)&g_cnt[base + 4];
        loc[0] = a.x; loc[1] = a.y; loc[2] = a.z; loc[3] = a.w;
        loc[4] = c.x; loc[5] = c.y; loc[6] = c.z; loc[7] = c.w;
        s = a.x + a.y + a.z + a.w + c.x + c.y + c.z + c.w;
    } else {
#pragma unroll
        for (int i = 0; i < 8; i++) {
            int idx = base + i;
            loc[i] = (idx < n) ? g_cnt[idx] : 0;
            s += loc[i];
        }
    }
    sh[t] = s;
    __syncthreads();
    for (int off = 1; off < 256; off <<= 1) {
        int v = (t >= off) ? sh[t - off] : 0;
        __syncthreads();
        sh[t] += v;
        __syncthreads();
    }
    int pre = g_boff[b] + ((t > 0) ? sh[t - 1] : 0);
    if (base + 8 <= n) {
        int rs[8];
        float dv[8];
#pragma unroll
        for (int i = 0; i < 8; i++) {
            rs[i] = pre;
            dv[i] = rsqrtf((float)(loc[i] + 1));
            pre += loc[i];
        }
        *(int4*)&g_rowstart[base]     = make_int4(rs[0], rs[1], rs[2], rs[3]);
        *(int4*)&g_rowstart[base + 4] = make_int4(rs[4], rs[5], rs[6], rs[7]);
        *(int4*)&g_cursor[base]       = make_int4(rs[0], rs[1], rs[2], rs[3]);
        *(int4*)&g_cursor[base + 4]   = make_int4(rs[4], rs[5], rs[6], rs[7]);
        *(float4*)&g_dinv[base]       = make_float4(dv[0], dv[1], dv[2], dv[3]);
        *(float4*)&g_dinv[base + 4]   = make_float4(dv[4], dv[5], dv[6], dv[7]);
    } else {
#pragma unroll
        for (int i = 0; i < 8; i++) {
            int idx = base + i;
            if (idx < n) {
                g_rowstart[idx] = pre;
                g_cursor[idx]   = pre;
                g_dinv[idx]     = rsqrtf((float)(loc[i] + 1));
                pre += loc[i];
            }
        }
    }
}

__global__ void place_kernel(const int* __restrict__ src, const int* __restrict__ dst, int e) {
    int i = blockIdx.x * blockDim.x + threadIdx.x;
    if (i < e) {
        int d = dst[i];
        int p = atomicAdd(&g_cursor[d], 1);
        g_csrc[p] = src[i];
    }
}

// ---------------- GEMM: C = A @ W over rows [r0, r1);  W:[128,128] ----------------
__global__ __launch_bounds__(256) void gemm_nk128(const float* __restrict__ A,
                                                  const float* __restrict__ W,
                                                  float* __restrict__ C,
                                                  int r0, int r1) {
    __shared__ float As[16][128];
    __shared__ float Bs[16][128];
    int m0 = r0 + blockIdx.x * 128;
    int t = threadIdx.x;
    int tr = (t >> 4) * 8;
    int tc = (t & 15) * 8;
    unsigned long long acc2[8][4];
#pragma unroll
    for (int r = 0; r < 8; r++)
#pragma unroll
        for (int c = 0; c < 4; c++) acc2[r][c] = 0ULL;

    for (int k0 = 0; k0 < 128; k0 += 16) {
#pragma unroll
        for (int j = 0; j < 2; j++) {
            int flat = t * 8 + j * 4;
            int row = flat >> 4, kk = flat & 15;
            float4 v = make_float4(0.f, 0.f, 0.f, 0.f);
            if (m0 + row < r1)
                v = *(const float4*)(A + (size_t)(m0 + row) * 128 + k0 + kk);
            As[kk + 0][row] = v.x;
            As[kk + 1][row] = v.y;
            As[kk + 2][row] = v.z;
            As[kk + 3][row] = v.w;
        }
#pragma unroll
        for (int j = 0; j < 2; j++) {
            int flat = t * 8 + j * 4;
            int kr = flat >> 7, cc = flat & 127;
            *(float4*)&Bs[kr][cc] = *(const float4*)(W + (size_t)(k0 + kr) * 128 + cc);
        }
        __syncthreads();
#pragma unroll
        for (int k = 0; k < 16; k++) {
            float4 a0 = *(float4*)&As[k][tr];
            float4 a1 = *(float4*)&As[k][tr + 4];
            ulonglong2 b0 = *(ulonglong2*)&Bs[k][tc];
            ulonglong2 b1 = *(ulonglong2*)&Bs[k][tc + 4];
            float a[8] = {a0.x, a0.y, a0.z, a0.w, a1.x, a1.y, a1.z, a1.w};
#pragma unroll
            for (int r = 0; r < 8; r++) {
                unsigned long long ar = pack2_dup(a[r]);
                fma2(acc2[r][0], ar, b0.x);
                fma2(acc2[r][1], ar, b0.y);
                fma2(acc2[r][2], ar, b1.x);
                fma2(acc2[r][3], ar, b1.y);
            }
        }
        __syncthreads();
    }
#pragma unroll
    for (int r = 0; r < 8; r++) {
        int row = m0 + tr + r;
        if (row < r1) {
            ulonglong2 s0; s0.x = acc2[r][0]; s0.y = acc2[r][1];
            ulonglong2 s1; s1.x = acc2[r][2]; s1.y = acc2[r][3];
            *(ulonglong2*)(C + (size_t)row * 128 + tc)     = s0;
            *(ulonglong2*)(C + (size_t)row * 128 + tc + 4) = s1;
        }
    }
}

// ---------------- Aggregation over nodes [r0, r1): warp per node, unroll-4 ----------------
__global__ __launch_bounds__(256) void aggregate_kernel(const float* __restrict__ G,
                                                        const float* __restrict__ bias,
                                                        float* O, const float* resid,
                                                        int has_resid, int r0, int r1) {
    int warp = r0 + ((blockIdx.x * blockDim.x + threadIdx.x) >> 5);
    int lane = threadIdx.x & 31;
    if (warp >= r1) return;
    int s = g_rowstart[warp];
    int e = g_rowstart[warp + 1];
    const float4* G4 = (const float4*)G;
    size_t self = (size_t)warp * 32 + lane;
    float d = g_dinv[warp];
    float4 sv = G4[self];
    float4 acc = make_float4(sv.x * d, sv.y * d, sv.z * d, sv.w * d);

    int i = s;
    for (; i + 3 < e; i += 4) {
        int j0 = g_csrc[i];
        int j1 = g_csrc[i + 1];
        int j2 = g_csrc[i + 2];
        int j3 = g_csrc[i + 3];
        float d0 = g_dinv[j0], d1 = g_dinv[j1], d2 = g_dinv[j2], d3 = g_dinv[j3];
        float4 v0 = G4[(size_t)j0 * 32 + lane];
        float4 v1 = G4[(size_t)j1 * 32 + lane];
        float4 v2 = G4[(size_t)j2 * 32 + lane];
        float4 v3 = G4[(size_t)j3 * 32 + lane];
        acc.x = fmaf(v0.x, d0, acc.x); acc.y = fmaf(v0.y, d0, acc.y);
        acc.z = fmaf(v0.z, d0, acc.z); acc.w = fmaf(v0.w, d0, acc.w);
        acc.x = fmaf(v1.x, d1, acc.x); acc.y = fmaf(v1.y, d1, acc.y);
        acc.z = fmaf(v1.z, d1, acc.z); acc.w = fmaf(v1.w, d1, acc.w);
        acc.x = fmaf(v2.x, d2, acc.x); acc.y = fmaf(v2.y, d2, acc.y);
        acc.z = fmaf(v2.z, d2, acc.z); acc.w = fmaf(v2.w, d2, acc.w);
        acc.x = fmaf(v3.x, d3, acc.x); acc.y = fmaf(v3.y, d3, acc.y);
        acc.z = fmaf(v3.z, d3, acc.z); acc.w = fmaf(v3.w, d3, acc.w);
    }
    for (; i < e; i++) {
        int j = g_csrc[i];
        float dj = g_dinv[j];
        float4 v = G4[(size_t)j * 32 + lane];
        acc.x = fmaf(v.x, dj, acc.x); acc.y = fmaf(v.y, dj, acc.y);
        acc.z = fmaf(v.z, dj, acc.z); acc.w = fmaf(v.w, dj, acc.w);
    }

    float4 b = ((const float4*)bias)[lane];
    acc.x = fmaxf(fmaf(acc.x, d, b.x), 0.f);
    acc.y = fmaxf(fmaf(acc.y, d, b.y), 0.f);
    acc.z = fmaxf(fmaf(acc.z, d, b.z), 0.f);
    acc.w = fmaxf(fmaf(acc.w, d, b.w), 0.f);
    if (has_resid) {
        float4 r = ((const float4*)resid)[self];
        acc.x += r.x; acc.y += r.y; acc.z += r.z; acc.w += r.w;
    }
    ((float4*)O)[self] = acc;
}

// ---------------- Output GEMM over rows [r0, r1): out = S @ Wc + bc ----------------
__global__ __launch_bounds__(256) void gemm_out_kernel(const float* __restrict__ S,
                                                       const float* __restrict__ Wc,
                                                       const float* __restrict__ bc,
                                                       float* __restrict__ out,
                                                       int r0, int r1) {
    __shared__ float Ws[128][40];
    __shared__ float Ss[128][33];
    __shared__ float bs[40];
    int t = threadIdx.x;
    int m0 = r0 + blockIdx.x * 128;
    for (int i = t; i < 128 * 40; i += 256) Ws[i / 40][i % 40] = Wc[i];
    if (t < 40) bs[t] = bc[t];

    int c0 = t & 7;
    int rq = t >> 3;
    float acc[4][5];
#pragma unroll
    for (int r = 0; r < 4; r++)
#pragma unroll
        for (int j = 0; j < 5; j++) acc[r][j] = 0.0f;

    for (int k0 = 0; k0 < 128; k0 += 32) {
        __syncthreads();
#pragma unroll
        for (int j = 0; j < 4; j++) {
            int flat = t * 16 + j * 4;
            int row = flat >> 5, kk = flat & 31;
            float4 v = make_float4(0.f, 0.f, 0.f, 0.f);
            if (m0 + row < r1)
                v = *(const float4*)(S + (size_t)(m0 + row) * 128 + k0 + kk);
            Ss[row][kk + 0] = v.x;
            Ss[row][kk + 1] = v.y;
            Ss[row][kk + 2] = v.z;
            Ss[row][kk + 3] = v.w;
        }
        __syncthreads();
#pragma unroll 8
        for (int k = 0; k < 32; k++) {
            float w0 = Ws[k0 + k][c0];
            float w1 = Ws[k0 + k][c0 + 8];
            float w2 = Ws[k0 + k][c0 + 16];
            float w3 = Ws[k0 + k][c0 + 24];
            float w4 = Ws[k0 + k][c0 + 32];
#pragma unroll
            for (int r = 0; r < 4; r++) {
                float a = Ss[rq * 4 + r][k];
                acc[r][0] += a * w0;
                acc[r][1] += a * w1;
                acc[r][2] += a * w2;
                acc[r][3] += a * w3;
                acc[r][4] += a * w4;
            }
        }
    }
#pragma unroll
    for (int r = 0; r < 4; r++) {
        int row = m0 + rq * 4 + r;
        if (row < r1) {
#pragma unroll
            for (int j = 0; j < 5; j++)
                out[(size_t)row * 40 + c0 + 8 * j] = acc[r][j] + bs[c0 + 8 * j];
        }
    }
}

// ---------------- launch ----------------
extern "C" void kernel_launch(void* const* d_in, const int* in_sizes, int n_in,
                              void* d_out, int out_size) {
    const float* x  = (const float*)d_in[0];
    const float* W1 = (const float*)d_in[1];
    const float* b1 = (const float*)d_in[2];
    const float* W2 = (const float*)d_in[3];
    const float* b2 = (const float*)d_in[4];
    const float* Wc = (const float*)d_in[5];
    const float* bc = (const float*)d_in[6];
    const int*   ei = (const int*)d_in[7];

    int N = in_sizes[0] / FDIM;
    int E = in_sizes[7] / 2;
    if (N > NMAX) N = NMAX;
    if (E > EMAX) E = EMAX;
    const int* src = ei;
    const int* dst = ei + E;

    float *G, *G2, *O;
    cudaGetSymbolAddress((void**)&G,  g_bufG);
    cudaGetSymbolAddress((void**)&G2, g_bufG2);
    cudaGetSymbolAddress((void**)&O,  g_bufO);

    static cudaStream_t s2 = nullptr;
    static cudaEvent_t ev_fork = nullptr, ev_csr = nullptr, ev_g2 = nullptr, ev_end = nullptr;
    static cudaEvent_t evA[NCHUNK], evB[NCHUNK];
    if (s2 == nullptr) {
        cudaStreamCreateWithFlags(&s2, cudaStreamNonBlocking);
        cudaEventCreateWithFlags(&ev_fork, cudaEventDisableTiming);
        cudaEventCreateWithFlags(&ev_csr, cudaEventDisableTiming);
        cudaEventCreateWithFlags(&ev_g2, cudaEventDisableTiming);
        cudaEventCreateWithFlags(&ev_end, cudaEventDisableTiming);
        for (int c = 0; c < NCHUNK; c++) {
            cudaEventCreateWithFlags(&evA[c], cudaEventDisableTiming);
            cudaEventCreateWithFlags(&evB[c], cudaEventDisableTiming);
        }
    }

    int nscanblk = (N + SCAN_BS - 1) / SCAN_BS;
    int chunk = (N + NCHUNK - 1) / NCHUNK;

    // Fork: CSR build on s2, concurrent with GEMM1 on stream 0.
    cudaEventRecord(ev_fork, 0);
    cudaStreamWaitEvent(s2, ev_fork, 0);
    zero_cnt_kernel<<<(N + 8 + 255) / 256, 256, 0, s2>>>(N);
    count_kernel<<<(E + 255) / 256, 256, 0, s2>>>(dst, E);
    scan1_kernel<<<nscanblk, 256, 0, s2>>>(N);
    scan2_kernel<<<1, 32, 0, s2>>>(nscanblk, N, E);
    scan3_kernel<<<nscanblk, 256, 0, s2>>>(N);
    place_kernel<<<(E + 255) / 256, 256, 0, s2>>>(src, dst, E);
    cudaEventRecord(ev_csr, s2);

    // GEMM1 (full): h1 = x @ W1   (independent of CSR)
    gemm_nk128<<<(N + 127) / 128, 256>>>(x, W1, G, 0, N);

    // agg1 needs GEMM1 + CSR.
    cudaStreamWaitEvent(0, ev_csr, 0);

    // Pipeline 1: agg1 chunks (reads G globally, writes O rows) on stream 0;
    //             GEMM2 chunks (reads O rows, writes G2 rows) on s2.
    // G2 != G -> no aliasing with agg1's global gathers.
    for (int c = 0; c < NCHUNK; c++) {
        int r0 = c * chunk;
        int r1 = (r0 + chunk < N) ? r0 + chunk : N;
        if (r0 >= r1) { cudaEventRecord(evA[c], 0); continue; }
        int nwarp = r1 - r0;
        aggregate_kernel<<<(nwarp * 32 + 255) / 256, 256>>>(G, b1, O, nullptr, 0, r0, r1);
        cudaEventRecord(evA[c], 0);
        cudaStreamWaitEvent(s2, evA[c], 0);
        gemm_nk128<<<(nwarp + 127) / 128, 256, 0, s2>>>(O, W2, G2, r0, r1);
    }
    cudaEventRecord(ev_g2, s2);
    cudaStreamWaitEvent(0, ev_g2, 0);   // agg2 gathers G2 globally -> needs ALL of GEMM2

    // Pipeline 2: agg2 chunks (reads G2 globally + O self-rows, writes O rows) on stream 0;
    //             outGEMM chunks (reads O rows, writes d_out rows) on s2.
    for (int c = 0; c < NCHUNK; c++) {
        int r0 = c * chunk;
        int r1 = (r0 + chunk < N) ? r0 + chunk : N;
        if (r0 >= r1) { cudaEventRecord(evB[c], 0); continue; }
        int nwarp = r1 - r0;
        aggregate_kernel<<<(nwarp * 32 + 255) / 256, 256>>>(G2, b2, O, O, 1, r0, r1);
        cudaEventRecord(evB[c], 0);
        cudaStreamWaitEvent(s2, evB[c], 0);
        gemm_out_kernel<<<(nwarp + 127) / 128, 256, 0, s2>>>(O, Wc, bc, (float*)d_out, r0, r1);
    }

    // Join s2 back to stream 0 so the capture sees all work complete.
    cudaEventRecord(ev_end, s2);
    cudaStreamWaitEvent(0, ev_end, 0);
}

// round 12
// speedup vs baseline: 1.2426x; 1.2426x over previous
#include <cuda_runtime.h>
#include <cuda_fp16.h>
#include <math.h>
#include <stdint.h>

// Problem-size maxima (fixed by the dataset: N=100000, E=1600000, F=H=128, OUT=40)
#define NMAX 100000
#define EMAX 1600000
#define FDIM 128
#define SCAN_BS 2048

// ---------------- scratch (static device globals; no allocation) ----------------
__device__ __align__(16) __half g_bufH[(size_t)NMAX * FDIM];  // h (fp16) — gather source, reused for both layers
__device__ __align__(16) float  g_bufO[(size_t)NMAX * FDIM];  // out1, then s = out2+out1 (fp32)
__device__ float g_dinv[NMAX];
__device__ __align__(16) int g_cnt[NMAX + 8];
__device__ __align__(16) int g_rowstart[NMAX + 8];
__device__ __align__(16) int g_cursor[NMAX + 8];
__device__ int   g_csrc[EMAX];
__device__ int   g_bsum[64];
__device__ int   g_boff[64];

// ---------------- packed fp32x2 helpers ----------------
__device__ __forceinline__ unsigned long long pack2_dup(float x) {
    unsigned long long r;
    asm("mov.b64 %0, {%1, %1};" : "=l"(r) : "f"(x));
    return r;
}
__device__ __forceinline__ void fma2(unsigned long long& d,
                                     unsigned long long a,
                                     unsigned long long b) {
    asm("fma.rn.f32x2 %0, %1, %2, %0;" : "+l"(d) : "l"(a), "l"(b));
}

// ---------------- CSR build ----------------
__global__ void zero_cnt_kernel(int n) {
    int i = blockIdx.x * blockDim.x + threadIdx.x;
    if (i < n + 8) g_cnt[i] = 0;
}

__global__ void count_kernel(const int* __restrict__ dst, int e) {
    int i = blockIdx.x * blockDim.x + threadIdx.x;
    if (i < e) atomicAdd(&g_cnt[dst[i]], 1);
}

__global__ __launch_bounds__(256) void scan1_kernel(int n) {
    __shared__ int red[256];
    int b = blockIdx.x, t = threadIdx.x;
    int base = b * SCAN_BS + t * 8;
    int s = 0;
    if (base + 8 <= n) {
        int4 a = *(const int4*)&g_cnt[base];
        int4 c = *(const int4*)&g_cnt[base + 4];
        s = a.x + a.y + a.z + a.w + c.x + c.y + c.z + c.w;
    } else {
        for (int i = 0; i < 8; i++) {
            int idx = base + i;
            if (idx < n) s += g_cnt[idx];
        }
    }
    red[t] = s;
    __syncthreads();
    for (int off = 128; off > 0; off >>= 1) {
        if (t < off) red[t] += red[t + off];
        __syncthreads();
    }
    if (t == 0) g_bsum[b] = red[0];
}

__global__ void scan2_kernel(int nb, int n, int e_total) {
    if (threadIdx.x == 0 && blockIdx.x == 0) {
        int acc = 0;
        for (int i = 0; i < nb; i++) {
            g_boff[i] = acc;
            acc += g_bsum[i];
        }
        g_rowstart[n] = e_total;
    }
}

__global__ __launch_bounds__(256) void scan3_kernel(int n) {
    __shared__ int sh[256];
    int b = blockIdx.x, t = threadIdx.x;
    int base = b * SCAN_BS + t * 8;
    int loc[8];
    int s = 0;
    if (base + 8 <= n) {
        int4 a = *(const int4*)&g_cnt[base];
        int4 c = *(const int4*)&g_cnt[base + 4];
        loc[0] = a.x; loc[1] = a.y; loc[2] = a.z; loc[3] = a.w;
        loc[4] = c.x; loc[5] = c.y; loc[6] = c.z; loc[7] = c.w;
        s = a.x + a.y + a.z + a.w + c.x + c.y + c.z + c.w;
    } else {
#pragma unroll
        for (int i = 0; i < 8; i++) {
            int idx = base + i;
            loc[i] = (idx < n) ? g_cnt[idx] : 0;
            s += loc[i];
        }
    }
    sh[t] = s;
    __syncthreads();
    for (int off = 1; off < 256; off <<= 1) {
        int v = (t >= off) ? sh[t - off] : 0;
        __syncthreads();
        sh[t] += v;
        __syncthreads();
    }
    int pre = g_boff[b] + ((t > 0) ? sh[t - 1] : 0);
    if (base + 8 <= n) {
        int rs[8];
        float dv[8];
#pragma unroll
        for (int i = 0; i < 8; i++) {
            rs[i] = pre;
            dv[i] = rsqrtf((float)(loc[i] + 1));
            pre += loc[i];
        }
        *(int4*)&g_rowstart[base]     = make_int4(rs[0], rs[1], rs[2], rs[3]);
        *(int4*)&g_rowstart[base + 4] = make_int4(rs[4], rs[5], rs[6], rs[7]);
        *(int4*)&g_cursor[base]       = make_int4(rs[0], rs[1], rs[2], rs[3]);
        *(int4*)&g_cursor[base + 4]   = make_int4(rs[4], rs[5], rs[6], rs[7]);
        *(float4*)&g_dinv[base]       = make_float4(dv[0], dv[1], dv[2], dv[3]);
        *(float4*)&g_dinv[base + 4]   = make_float4(dv[4], dv[5], dv[6], dv[7]);
    } else {
#pragma unroll
        for (int i = 0; i < 8; i++) {
            int idx = base + i;
            if (idx < n) {
                g_rowstart[idx] = pre;
                g_cursor[idx]   = pre;
                g_dinv[idx]     = rsqrtf((float)(loc[i] + 1));
                pre += loc[i];
            }
        }
    }
}

__global__ void place_kernel(const int* __restrict__ src, const int* __restrict__ dst, int e) {
    int i = blockIdx.x * blockDim.x + threadIdx.x;
    if (i < e) {
        int d = dst[i];
        int p = atomicAdd(&g_cursor[d], 1);
        g_csrc[p] = src[i];
    }
}

// ---------------- GEMM: H = fp16(A @ W);  A:[n,128] fp32, W:[128,128] fp32 ----------------
// Tile: 128x128, BK=16, 256 threads, 8x8 micro-tile, fp32x2 accumulators, fp16 output.
__global__ __launch_bounds__(256) void gemm_nk128(const float* __restrict__ A,
                                                  const float* __restrict__ W,
                                                  __half* __restrict__ H, int n) {
    __shared__ float As[16][128];
    __shared__ float Bs[16][128];
    int m0 = blockIdx.x * 128;
    int t = threadIdx.x;
    int tr = (t >> 4) * 8;
    int tc = (t & 15) * 8;
    unsigned long long acc2[8][4];
#pragma unroll
    for (int r = 0; r < 8; r++)
#pragma unroll
        for (int c = 0; c < 4; c++) acc2[r][c] = 0ULL;

    for (int k0 = 0; k0 < 128; k0 += 16) {
#pragma unroll
        for (int j = 0; j < 2; j++) {
            int flat = t * 8 + j * 4;
            int row = flat >> 4, kk = flat & 15;
            float4 v = make_float4(0.f, 0.f, 0.f, 0.f);
            if (m0 + row < n)
                v = *(const float4*)(A + (size_t)(m0 + row) * 128 + k0 + kk);
            As[kk + 0][row] = v.x;
            As[kk + 1][row] = v.y;
            As[kk + 2][row] = v.z;
            As[kk + 3][row] = v.w;
        }
#pragma unroll
        for (int j = 0; j < 2; j++) {
            int flat = t * 8 + j * 4;
            int kr = flat >> 7, cc = flat & 127;
            *(float4*)&Bs[kr][cc] = *(const float4*)(W + (size_t)(k0 + kr) * 128 + cc);
        }
        __syncthreads();
#pragma unroll
        for (int k = 0; k < 16; k++) {
            float4 a0 = *(float4*)&As[k][tr];
            float4 a1 = *(float4*)&As[k][tr + 4];
            ulonglong2 b0 = *(ulonglong2*)&Bs[k][tc];
            ulonglong2 b1 = *(ulonglong2*)&Bs[k][tc + 4];
            float a[8] = {a0.x, a0.y, a0.z, a0.w, a1.x, a1.y, a1.z, a1.w};
#pragma unroll
            for (int r = 0; r < 8; r++) {
                unsigned long long ar = pack2_dup(a[r]);
                fma2(acc2[r][0], ar, b0.x);
                fma2(acc2[r][1], ar, b0.y);
                fma2(acc2[r][2], ar, b1.x);
                fma2(acc2[r][3], ar, b1.y);
            }
        }
        __syncthreads();
    }
#pragma unroll
    for (int r = 0; r < 8; r++) {
        int row = m0 + tr + r;
        if (row < n) {
            __half2 h[4];
#pragma unroll
            for (int c = 0; c < 4; c++) {
                float2 f = *(float2*)&acc2[r][c];
                h[c] = __float22half2_rn(f);
            }
            // 8 halfs = 16 bytes, (row*128+tc)*2 bytes is 16B-aligned (tc multiple of 8)
            *(uint4*)(H + (size_t)row * 128 + tc) = *(uint4*)h;
        }
    }
}

// ---------------- Aggregation: warp per node, fp16 gathers, fp32 accumulation ----------------
// O[i] = relu( dinv[i] * ( sum_j h[j]*dinv[j]  +  h[i]*dinv[i] ) + bias )  [+ resid[i]]
__global__ __launch_bounds__(256) void aggregate_kernel(const __half* __restrict__ H,
                                                        const float* __restrict__ bias,
                                                        float* O, const float* resid,
                                                        int has_resid, int n) {
    int warp = (blockIdx.x * blockDim.x + threadIdx.x) >> 5;
    int lane = threadIdx.x & 31;
    if (warp >= n) return;
    int s = g_rowstart[warp];
    int e = g_rowstart[warp + 1];
    const uint2* H8 = (const uint2*)H;   // 4 halfs per uint2; row stride = 32 uint2 (256 B)
    size_t self = (size_t)warp * 32 + lane;
    float d = g_dinv[warp];

    uint2 raw = H8[self];
    __half2 s0 = *(__half2*)&raw.x, s1 = *(__half2*)&raw.y;
    float2 f0 = __half22float2(s0), f1 = __half22float2(s1);
    float4 acc = make_float4(f0.x * d, f0.y * d, f1.x * d, f1.y * d);

    int i = s;
    for (; i + 3 < e; i += 4) {                  // 4 independent gathers in flight
        int j0 = g_csrc[i];
        int j1 = g_csrc[i + 1];
        int j2 = g_csrc[i + 2];
        int j3 = g_csrc[i + 3];
        float d0 = g_dinv[j0], d1 = g_dinv[j1], d2 = g_dinv[j2], d3 = g_dinv[j3];
        uint2 r0 = H8[(size_t)j0 * 32 + lane];
        uint2 r1 = H8[(size_t)j1 * 32 + lane];
        uint2 r2 = H8[(size_t)j2 * 32 + lane];
        uint2 r3 = H8[(size_t)j3 * 32 + lane];
        {
            float2 a = __half22float2(*(__half2*)&r0.x), b = __half22float2(*(__half2*)&r0.y);
            acc.x = fmaf(a.x, d0, acc.x); acc.y = fmaf(a.y, d0, acc.y);
            acc.z = fmaf(b.x, d0, acc.z); acc.w = fmaf(b.y, d0, acc.w);
        }
        {
            float2 a = __half22float2(*(__half2*)&r1.x), b = __half22float2(*(__half2*)&r1.y);
            acc.x = fmaf(a.x, d1, acc.x); acc.y = fmaf(a.y, d1, acc.y);
            acc.z = fmaf(b.x, d1, acc.z); acc.w = fmaf(b.y, d1, acc.w);
        }
        {
            float2 a = __half22float2(*(__half2*)&r2.x), b = __half22float2(*(__half2*)&r2.y);
            acc.x = fmaf(a.x, d2, acc.x); acc.y = fmaf(a.y, d2, acc.y);
            acc.z = fmaf(b.x, d2, acc.z); acc.w = fmaf(b.y, d2, acc.w);
        }
        {
            float2 a = __half22float2(*(__half2*)&r3.x), b = __half22float2(*(__half2*)&r3.y);
            acc.x = fmaf(a.x, d3, acc.x); acc.y = fmaf(a.y, d3, acc.y);
            acc.z = fmaf(b.x, d3, acc.z); acc.w = fmaf(b.y, d3, acc.w);
        }
    }
    for (; i < e; i++) {
        int j = g_csrc[i];
        float dj = g_dinv[j];
        uint2 r = H8[(size_t)j * 32 + lane];
        float2 a = __half22float2(*(__half2*)&r.x), b = __half22float2(*(__half2*)&r.y);
        acc.x = fmaf(a.x, dj, acc.x); acc.y = fmaf(a.y, dj, acc.y);
        acc.z = fmaf(b.x, dj, acc.z); acc.w = fmaf(b.y, dj, acc.w);
    }

    float4 b = ((const float4*)bias)[lane];
    acc.x = fmaxf(fmaf(acc.x, d, b.x), 0.f);
    acc.y = fmaxf(fmaf(acc.y, d, b.y), 0.f);
    acc.z = fmaxf(fmaf(acc.z, d, b.z), 0.f);
    acc.w = fmaxf(fmaf(acc.w, d, b.w), 0.f);
    if (has_resid) {
        float4 r = ((const float4*)resid)[(size_t)warp * 32 + lane];
        acc.x += r.x; acc.y += r.y; acc.z += r.z; acc.w += r.w;
    }
    ((float4*)O)[(size_t)warp * 32 + lane] = acc;
}

// ---------------- Output GEMM: out = S @ Wc + bc;  S:[n,128] fp32, Wc:[128,40] ----------------
__global__ __launch_bounds__(256) void gemm_out_kernel(const float* __restrict__ S,
                                                       const float* __restrict__ Wc,
                                                       const float* __restrict__ bc,
                                                       float* __restrict__ out, int n) {
    __shared__ float Ws[128][40];
    __shared__ float Ss[128][33];
    __shared__ float bs[40];
    int t = threadIdx.x;
    int m0 = blockIdx.x * 128;
    for (int i = t; i < 128 * 40; i += 256) Ws[i / 40][i % 40] = Wc[i];
    if (t < 40) bs[t] = bc[t];

    int c0 = t & 7;
    int rq = t >> 3;
    float acc[4][5];
#pragma unroll
    for (int r = 0; r < 4; r++)
#pragma unroll
        for (int j = 0; j < 5; j++) acc[r][j] = 0.0f;

    for (int k0 = 0; k0 < 128; k0 += 32) {
        __syncthreads();
#pragma unroll
        for (int j = 0; j < 4; j++) {
            int flat = t * 16 + j * 4;
            int row = flat >> 5, kk = flat & 31;
            float4 v = make_float4(0.f, 0.f, 0.f, 0.f);
            if (m0 + row < n)
                v = *(const float4*)(S + (size_t)(m0 + row) * 128 + k0 + kk);
            Ss[row][kk + 0] = v.x;
            Ss[row][kk + 1] = v.y;
            Ss[row][kk + 2] = v.z;
            Ss[row][kk + 3] = v.w;
        }
        __syncthreads();
#pragma unroll 8
        for (int k = 0; k < 32; k++) {
            float w0 = Ws[k0 + k][c0];
            float w1 = Ws[k0 + k][c0 + 8];
            float w2 = Ws[k0 + k][c0 + 16];
            float w3 = Ws[k0 + k][c0 + 24];
            float w4 = Ws[k0 + k][c0 + 32];
#pragma unroll
            for (int r = 0; r < 4; r++) {
                float a = Ss[rq * 4 + r][k];
                acc[r][0] += a * w0;
                acc[r][1] += a * w1;
                acc[r][2] += a * w2;
                acc[r][3] += a * w3;
                acc[r][4] += a * w4;
            }
        }
    }
#pragma unroll
    for (int r = 0; r < 4; r++) {
        int row = m0 + rq * 4 + r;
        if (row < n) {
#pragma unroll
            for (int j = 0; j < 5; j++)
                out[(size_t)row * 40 + c0 + 8 * j] = acc[r][j] + bs[c0 + 8 * j];
        }
    }
}

// ---------------- launch (R8 serial schedule: CSR forked under GEMM1 only) ----------------
extern "C" void kernel_launch(void* const* d_in, const int* in_sizes, int n_in,
                              void* d_out, int out_size) {
    const float* x  = (const float*)d_in[0];
    const float* W1 = (const float*)d_in[1];
    const float* b1 = (const float*)d_in[2];
    const float* W2 = (const float*)d_in[3];
    const float* b2 = (const float*)d_in[4];
    const float* Wc = (const float*)d_in[5];
    const float* bc = (const float*)d_in[6];
    const int*   ei = (const int*)d_in[7];

    int N = in_sizes[0] / FDIM;
    int E = in_sizes[7] / 2;
    if (N > NMAX) N = NMAX;
    if (E > EMAX) E = EMAX;
    const int* src = ei;
    const int* dst = ei + E;

    __half* H;
    float* O;
    cudaGetSymbolAddress((void**)&H, g_bufH);
    cudaGetSymbolAddress((void**)&O, g_bufO);

    static cudaStream_t s2 = nullptr;
    static cudaEvent_t ev_fork = nullptr, ev_csr = nullptr;
    if (s2 == nullptr) {
        cudaStreamCreateWithFlags(&s2, cudaStreamNonBlocking);
        cudaEventCreateWithFlags(&ev_fork, cudaEventDisableTiming);
        cudaEventCreateWithFlags(&ev_csr, cudaEventDisableTiming);
    }

    int nscanblk  = (N + SCAN_BS - 1) / SCAN_BS;
    int gemm_grid = (N + 127) / 128;
    int agg_grid  = (N * 32 + 255) / 256;

    // Fork: CSR build on s2, concurrent with GEMM1 on stream 0.
    cudaEventRecord(ev_fork, 0);
    cudaStreamWaitEvent(s2, ev_fork, 0);
    zero_cnt_kernel<<<(N + 8 + 255) / 256, 256, 0, s2>>>(N);
    count_kernel<<<(E + 255) / 256, 256, 0, s2>>>(dst, E);
    scan1_kernel<<<nscanblk, 256, 0, s2>>>(N);
    scan2_kernel<<<1, 32, 0, s2>>>(nscanblk, N, E);
    scan3_kernel<<<nscanblk, 256, 0, s2>>>(N);
    place_kernel<<<(E + 255) / 256, 256, 0, s2>>>(src, dst, E);
    cudaEventRecord(ev_csr, s2);

    // Layer 1 GEMM: h1 = fp16(x @ W1)   (independent of CSR)
    gemm_nk128<<<gemm_grid, 256>>>(x, W1, H, N);

    // Join, then serial main chain (R8 schedule — measured faster than chunk pipelining).
    cudaStreamWaitEvent(0, ev_csr, 0);
    aggregate_kernel<<<agg_grid, 256>>>(H, b1, O, nullptr, 0, N);
    gemm_nk128<<<gemm_grid, 256>>>(O, W2, H, N);          // H reuse is safe: serial order
    aggregate_kernel<<<agg_grid, 256>>>(H, b2, O, O, 1, N);
    gemm_out_kernel<<<gemm_grid, 256>>>(O, Wc, bc, (float*)d_out, N);
}

// round 14
// speedup vs baseline: 1.6239x; 1.3069x over previous
#include <cuda_runtime.h>
#include <cuda_fp16.h>
#include <mma.h>
#include <math.h>
#include <stdint.h>

using namespace nvcuda;

// Problem-size maxima (fixed by the dataset: N=100000, E=1600000, F=H=128, OUT=40)
#define NMAX 100000
#define EMAX 1600000
#define FDIM 128
#define SCAN_BS 2048

// ---------------- scratch (static device globals; no allocation) ----------------
__device__ __align__(32) __half g_bufH[(size_t)NMAX * FDIM];  // h (fp16) — gather source
__device__ __align__(16) float  g_bufO[(size_t)NMAX * FDIM];  // out1, then s = out2+out1 (fp32)
__device__ __align__(32) __half g_W1h[FDIM * FDIM];           // W1 in fp16
__device__ __align__(32) __half g_W2h[FDIM * FDIM];           // W2 in fp16
__device__ float g_dinv[NMAX];
__device__ __align__(16) int g_cnt[NMAX + 8];
__device__ __align__(16) int g_rowstart[NMAX + 8];
__device__ __align__(16) int g_cursor[NMAX + 8];
__device__ int   g_csrc[EMAX];
__device__ int   g_bsum[64];
__device__ int   g_boff[64];

// ---------------- CSR build ----------------
__global__ void zero_cnt_kernel(int n) {
    int i = blockIdx.x * blockDim.x + threadIdx.x;
    if (i < n + 8) g_cnt[i] = 0;
}

__global__ void count_kernel(const int* __restrict__ dst, int e) {
    int i = blockIdx.x * blockDim.x + threadIdx.x;
    if (i < e) atomicAdd(&g_cnt[dst[i]], 1);
}

__global__ __launch_bounds__(256) void scan1_kernel(int n) {
    __shared__ int red[256];
    int b = blockIdx.x, t = threadIdx.x;
    int base = b * SCAN_BS + t * 8;
    int s = 0;
    if (base + 8 <= n) {
        int4 a = *(const int4*)&g_cnt[base];
        int4 c = *(const int4*)&g_cnt[base + 4];
        s = a.x + a.y + a.z + a.w + c.x + c.y + c.z + c.w;
    } else {
        for (int i = 0; i < 8; i++) {
            int idx = base + i;
            if (idx < n) s += g_cnt[idx];
        }
    }
    red[t] = s;
    __syncthreads();
    for (int off = 128; off > 0; off >>= 1) {
        if (t < off) red[t] += red[t + off];
        __syncthreads();
    }
    if (t == 0) g_bsum[b] = red[0];
}

__global__ void scan2_kernel(int nb, int n, int e_total) {
    if (threadIdx.x == 0 && blockIdx.x == 0) {
        int acc = 0;
        for (int i = 0; i < nb; i++) {
            g_boff[i] = acc;
            acc += g_bsum[i];
        }
        g_rowstart[n] = e_total;
    }
}

__global__ __launch_bounds__(256) void scan3_kernel(int n) {
    __shared__ int sh[256];
    int b = blockIdx.x, t = threadIdx.x;
    int base = b * SCAN_BS + t * 8;
    int loc[8];
    int s = 0;
    if (base + 8 <= n) {
        int4 a = *(const int4*)&g_cnt[base];
        int4 c = *(const int4*)&g_cnt[base + 4];
        loc[0] = a.x; loc[1] = a.y; loc[2] = a.z; loc[3] = a.w;
        loc[4] = c.x; loc[5] = c.y; loc[6] = c.z; loc[7] = c.w;
        s = a.x + a.y + a.z + a.w + c.x + c.y + c.z + c.w;
    } else {
#pragma unroll
        for (int i = 0; i < 8; i++) {
            int idx = base + i;
            loc[i] = (idx < n) ? g_cnt[idx] : 0;
            s += loc[i];
        }
    }
    sh[t] = s;
    __syncthreads();
    for (int off = 1; off < 256; off <<= 1) {
        int v = (t >= off) ? sh[t - off] : 0;
        __syncthreads();
        sh[t] += v;
        __syncthreads();
    }
    int pre = g_boff[b] + ((t > 0) ? sh[t - 1] : 0);
    if (base + 8 <= n) {
        int rs[8];
        float dv[8];
#pragma unroll
        for (int i = 0; i < 8; i++) {
            rs[i] = pre;
            dv[i] = rsqrtf((float)(loc[i] + 1));
            pre += loc[i];
        }
        *(int4*)&g_rowstart[base]     = make_int4(rs[0], rs[1], rs[2], rs[3]);
        *(int4*)&g_rowstart[base + 4] = make_int4(rs[4], rs[5], rs[6], rs[7]);
        *(int4*)&g_cursor[base]       = make_int4(rs[0], rs[1], rs[2], rs[3]);
        *(int4*)&g_cursor[base + 4]   = make_int4(rs[4], rs[5], rs[6], rs[7]);
        *(float4*)&g_dinv[base]       = make_float4(dv[0], dv[1], dv[2], dv[3]);
        *(float4*)&g_dinv[base + 4]   = make_float4(dv[4], dv[5], dv[6], dv[7]);
    } else {
#pragma unroll
        for (int i = 0; i < 8; i++) {
            int idx = base + i;
            if (idx < n) {
                g_rowstart[idx] = pre;
                g_cursor[idx]   = pre;
                g_dinv[idx]     = rsqrtf((float)(loc[i] + 1));
                pre += loc[i];
            }
        }
    }
}

__global__ void place_kernel(const int* __restrict__ src, const int* __restrict__ dst, int e) {
    int i = blockIdx.x * blockDim.x + threadIdx.x;
    if (i < e) {
        int d = dst[i];
        int p = atomicAdd(&g_cursor[d], 1);
        g_csrc[p] = src[i];
    }
}

// ---------------- W fp32 -> fp16 conversion (128x128 = 16384 elems) ----------------
__global__ void convert_w_kernel(const float* __restrict__ W, __half* __restrict__ Wh) {
    int i = (blockIdx.x * 256 + threadIdx.x) * 4;   // 4096 threads x 4
    if (i < FDIM * FDIM) {
        float4 v = *(const float4*)(W + i);
        __half2 h0 = __floats2half2_rn(v.x, v.y);
        __half2 h1 = __floats2half2_rn(v.z, v.w);
        *(uint2*)(Wh + i) = make_uint2(*(unsigned*)&h0, *(unsigned*)&h1);
    }
}

// ---------------- Tensor-core GEMM: H = fp16(A @ W);  A fp32 [n,128], Wh fp16 [128,128] ----
// Block: 128x128 tile, 256 threads = 8 warps (2x4), warp tile 64x32, WMMA m16n16k16 fp32-acc.
__global__ __launch_bounds__(256) void gemm_tc(const float* __restrict__ A,
                                               const __half* __restrict__ Wh,
                                               __half* __restrict__ H, int n) {
    __shared__ __half As[128][144];        // ld=144 halves (mult of 8) -> wmma-legal, 36.9 KB
    __shared__ float  St[8][16][20];       // ld=20 floats (mult of 4) -> wmma-legal, 10.2 KB
    int t = threadIdx.x;
    int wid = t >> 5, lane = t & 31;
    int m0 = blockIdx.x * 128;

    // stage A tile fp32 -> fp16 (coalesced float4 loads)
#pragma unroll
    for (int it = 0; it < 16; it++) {
        int flat = (it * 256 + t) * 4;     // covers 128*128
        int row = flat >> 7, col = flat & 127;
        float4 v = make_float4(0.f, 0.f, 0.f, 0.f);
        if (m0 + row < n)
            v = *(const float4*)(A + (size_t)(m0 + row) * 128 + col);
        __half2 h0 = __floats2half2_rn(v.x, v.y);
        __half2 h1 = __floats2half2_rn(v.z, v.w);
        *(uint2*)&As[row][col] = make_uint2(*(unsigned*)&h0, *(unsigned*)&h1);
    }
    __syncthreads();

    int warp_m = wid >> 2;   // 0..1 -> rows warp_m*64
    int warp_n = wid & 3;    // 0..3 -> cols warp_n*32

    wmma::fragment<wmma::accumulator, 16, 16, 16, float> c[4][2];
#pragma unroll
    for (int i = 0; i < 4; i++)
#pragma unroll
        for (int j = 0; j < 2; j++) wmma::fill_fragment(c[i][j], 0.0f);

#pragma unroll
    for (int kk = 0; kk < 128; kk += 16) {
        wmma::fragment<wmma::matrix_a, 16, 16, 16, __half, wmma::row_major> a[4];
        wmma::fragment<wmma::matrix_b, 16, 16, 16, __half, wmma::row_major> b[2];
#pragma unroll
        for (int i = 0; i < 4; i++)
            wmma::load_matrix_sync(a[i], &As[warp_m * 64 + i * 16][kk], 144);
#pragma unroll
        for (int j = 0; j < 2; j++)
            wmma::load_matrix_sync(b[j], Wh + (size_t)kk * 128 + warp_n * 32 + j * 16, 128);
#pragma unroll
        for (int i = 0; i < 4; i++)
#pragma unroll
            for (int j = 0; j < 2; j++)
                wmma::mma_sync(c[i][j], a[i], b[j], c[i][j]);
    }

    // epilogue: fragment -> smem stage (ld=20, legal) -> fp16 gmem
#pragma unroll
    for (int i = 0; i < 4; i++) {
#pragma unroll
        for (int j = 0; j < 2; j++) {
            wmma::store_matrix_sync(&St[wid][0][0], c[i][j], 20, wmma::mem_row_major);
            __syncwarp();
            int r = lane >> 1;              // 16 rows, 2 lanes/row
            int cbase = (lane & 1) * 8;     // 8 cols/lane
            int grow = m0 + warp_m * 64 + i * 16 + r;
            if (grow < n) {
                __half hbuf[8];
#pragma unroll
                for (int q = 0; q < 8; q++) hbuf[q] = __float2half_rn(St[wid][r][cbase + q]);
                *(uint4*)(H + (size_t)grow * 128 + warp_n * 32 + j * 16 + cbase) = *(uint4*)hbuf;
            }
            __syncwarp();
        }
    }
}

// ---------------- Aggregation: warp per node, fp16 gathers, fp32 accumulation ----------------
__global__ __launch_bounds__(256) void aggregate_kernel(const __half* __restrict__ H,
                                                        const float* __restrict__ bias,
                                                        float* O, const float* resid,
                                                        int has_resid, int n) {
    int warp = (blockIdx.x * blockDim.x + threadIdx.x) >> 5;
    int lane = threadIdx.x & 31;
    if (warp >= n) return;
    int s = g_rowstart[warp];
    int e = g_rowstart[warp + 1];
    const uint2* H8 = (const uint2*)H;
    size_t self = (size_t)warp * 32 + lane;
    float d = g_dinv[warp];

    uint2 raw = H8[self];
    float2 f0 = __half22float2(*(__half2*)&raw.x), f1 = __half22float2(*(__half2*)&raw.y);
    float4 acc = make_float4(f0.x * d, f0.y * d, f1.x * d, f1.y * d);

    int i = s;
    for (; i + 3 < e; i += 4) {
        int j0 = g_csrc[i];
        int j1 = g_csrc[i + 1];
        int j2 = g_csrc[i + 2];
        int j3 = g_csrc[i + 3];
        float d0 = g_dinv[j0], d1 = g_dinv[j1], d2 = g_dinv[j2], d3 = g_dinv[j3];
        uint2 r0 = H8[(size_t)j0 * 32 + lane];
        uint2 r1 = H8[(size_t)j1 * 32 + lane];
        uint2 r2 = H8[(size_t)j2 * 32 + lane];
        uint2 r3 = H8[(size_t)j3 * 32 + lane];
        {
            float2 a = __half22float2(*(__half2*)&r0.x), b = __half22float2(*(__half2*)&r0.y);
            acc.x = fmaf(a.x, d0, acc.x); acc.y = fmaf(a.y, d0, acc.y);
            acc.z = fmaf(b.x, d0, acc.z); acc.w = fmaf(b.y, d0, acc.w);
        }
        {
            float2 a = __half22float2(*(__half2*)&r1.x), b = __half22float2(*(__half2*)&r1.y);
            acc.x = fmaf(a.x, d1, acc.x); acc.y = fmaf(a.y, d1, acc.y);
            acc.z = fmaf(b.x, d1, acc.z); acc.w = fmaf(b.y, d1, acc.w);
        }
        {
            float2 a = __half22float2(*(__half2*)&r2.x), b = __half22float2(*(__half2*)&r2.y);
            acc.x = fmaf(a.x, d2, acc.x); acc.y = fmaf(a.y, d2, acc.y);
            acc.z = fmaf(b.x, d2, acc.z); acc.w = fmaf(b.y, d2, acc.w);
        }
        {
            float2 a = __half22float2(*(__half2*)&r3.x), b = __half22float2(*(__half2*)&r3.y);
            acc.x = fmaf(a.x, d3, acc.x); acc.y = fmaf(a.y, d3, acc.y);
            acc.z = fmaf(b.x, d3, acc.z); acc.w = fmaf(b.y, d3, acc.w);
        }
    }
    for (; i < e; i++) {
        int j = g_csrc[i];
        float dj = g_dinv[j];
        uint2 r = H8[(size_t)j * 32 + lane];
        float2 a = __half22float2(*(__half2*)&r.x), b = __half22float2(*(__half2*)&r.y);
        acc.x = fmaf(a.x, dj, acc.x); acc.y = fmaf(a.y, dj, acc.y);
        acc.z = fmaf(b.x, dj, acc.z); acc.w = fmaf(b.y, dj, acc.w);
    }

    float4 b = ((const float4*)bias)[lane];
    acc.x = fmaxf(fmaf(acc.x, d, b.x), 0.f);
    acc.y = fmaxf(fmaf(acc.y, d, b.y), 0.f);
    acc.z = fmaxf(fmaf(acc.z, d, b.z), 0.f);
    acc.w = fmaxf(fmaf(acc.w, d, b.w), 0.f);
    if (has_resid) {
        float4 r = ((const float4*)resid)[self];
        acc.x += r.x; acc.y += r.y; acc.z += r.z; acc.w += r.w;
    }
    ((float4*)O)[self] = acc;
}

// ---------------- Output GEMM: out = S @ Wc + bc;  S:[n,128] fp32, Wc:[128,40] ----------------
__global__ __launch_bounds__(256) void gemm_out_kernel(const float* __restrict__ S,
                                                       const float* __restrict__ Wc,
                                                       const float* __restrict__ bc,
                                                       float* __restrict__ out, int n) {
    __shared__ float Ws[128][40];
    __shared__ float Ss[128][33];
    __shared__ float bs[40];
    int t = threadIdx.x;
    int m0 = blockIdx.x * 128;
    for (int i = t; i < 128 * 40; i += 256) Ws[i / 40][i % 40] = Wc[i];
    if (t < 40) bs[t] = bc[t];

    int c0 = t & 7;
    int rq = t >> 3;
    float acc[4][5];
#pragma unroll
    for (int r = 0; r < 4; r++)
#pragma unroll
        for (int j = 0; j < 5; j++) acc[r][j] = 0.0f;

    for (int k0 = 0; k0 < 128; k0 += 32) {
        __syncthreads();
#pragma unroll
        for (int j = 0; j < 4; j++) {
            int flat = t * 16 + j * 4;
            int row = flat >> 5, kk = flat & 31;
            float4 v = make_float4(0.f, 0.f, 0.f, 0.f);
            if (m0 + row < n)
                v = *(const float4*)(S + (size_t)(m0 + row) * 128 + k0 + kk);
            Ss[row][kk + 0] = v.x;
            Ss[row][kk + 1] = v.y;
            Ss[row][kk + 2] = v.z;
            Ss[row][kk + 3] = v.w;
        }
        __syncthreads();
#pragma unroll 8
        for (int k = 0; k < 32; k++) {
            float w0 = Ws[k0 + k][c0];
            float w1 = Ws[k0 + k][c0 + 8];
            float w2 = Ws[k0 + k][c0 + 16];
            float w3 = Ws[k0 + k][c0 + 24];
            float w4 = Ws[k0 + k][c0 + 32];
#pragma unroll
            for (int r = 0; r < 4; r++) {
                float a = Ss[rq * 4 + r][k];
                acc[r][0] += a * w0;
                acc[r][1] += a * w1;
                acc[r][2] += a * w2;
                acc[r][3] += a * w3;
                acc[r][4] += a * w4;
            }
        }
    }
#pragma unroll
    for (int r = 0; r < 4; r++) {
        int row = m0 + rq * 4 + r;
        if (row < n) {
#pragma unroll
            for (int j = 0; j < 5; j++)
                out[(size_t)row * 40 + c0 + 8 * j] = acc[r][j] + bs[c0 + 8 * j];
        }
    }
}

// ---------------- launch (serial main chain; CSR forked under GEMM1) ----------------
extern "C" void kernel_launch(void* const* d_in, const int* in_sizes, int n_in,
                              void* d_out, int out_size) {
    const float* x  = (const float*)d_in[0];
    const float* W1 = (const float*)d_in[1];
    const float* b1 = (const float*)d_in[2];
    const float* W2 = (const float*)d_in[3];
    const float* b2 = (const float*)d_in[4];
    const float* Wc = (const float*)d_in[5];
    const float* bc = (const float*)d_in[6];
    const int*   ei = (const int*)d_in[7];

    int N = in_sizes[0] / FDIM;
    int E = in_sizes[7] / 2;
    if (N > NMAX) N = NMAX;
    if (E > EMAX) E = EMAX;
    const int* src = ei;
    const int* dst = ei + E;

    __half *H, *W1h, *W2h;
    float* O;
    cudaGetSymbolAddress((void**)&H,   g_bufH);
    cudaGetSymbolAddress((void**)&O,   g_bufO);
    cudaGetSymbolAddress((void**)&W1h, g_W1h);
    cudaGetSymbolAddress((void**)&W2h, g_W2h);

    static cudaStream_t s2 = nullptr;
    static cudaEvent_t ev_fork = nullptr, ev_csr = nullptr;
    if (s2 == nullptr) {
        cudaStreamCreateWithFlags(&s2, cudaStreamNonBlocking);
        cudaEventCreateWithFlags(&ev_fork, cudaEventDisableTiming);
        cudaEventCreateWithFlags(&ev_csr, cudaEventDisableTiming);
    }

    int nscanblk  = (N + SCAN_BS - 1) / SCAN_BS;
    int gemm_grid = (N + 127) / 128;
    int agg_grid  = (N * 32 + 255) / 256;

    // Fork: CSR build on s2, concurrent with W conversion + GEMM1 on stream 0.
    cudaEventRecord(ev_fork, 0);
    cudaStreamWaitEvent(s2, ev_fork, 0);
    zero_cnt_kernel<<<(N + 8 + 255) / 256, 256, 0, s2>>>(N);
    count_kernel<<<(E + 255) / 256, 256, 0, s2>>>(dst, E);
    scan1_kernel<<<nscanblk, 256, 0, s2>>>(N);
    scan2_kernel<<<1, 32, 0, s2>>>(nscanblk, N, E);
    scan3_kernel<<<nscanblk, 256, 0, s2>>>(N);
    place_kernel<<<(E + 255) / 256, 256, 0, s2>>>(src, dst, E);
    cudaEventRecord(ev_csr, s2);

    // Weight conversions (tiny) + Layer 1 GEMM on stream 0.
    convert_w_kernel<<<16, 256>>>(W1, W1h);
    convert_w_kernel<<<16, 256>>>(W2, W2h);
    gemm_tc<<<gemm_grid, 256>>>(x, W1h, H, N);

    // Join, then serial main chain.
    cudaStreamWaitEvent(0, ev_csr, 0);
    aggregate_kernel<<<agg_grid, 256>>>(H, b1, O, nullptr, 0, N);
    gemm_tc<<<gemm_grid, 256>>>(O, W2h, H, N);
    aggregate_kernel<<<agg_grid, 256>>>(H, b2, O, O, 1, N);
    gemm_out_kernel<<<gemm_grid, 256>>>(O, Wc, bc, (float*)d_out, N);
}

// round 15
// speedup vs baseline: 1.6251x; 1.0007x over previous
#include <cuda_runtime.h>
#include <cuda_fp16.h>
#include <mma.h>
#include <math.h>
#include <stdint.h>

using namespace nvcuda;

// Problem-size maxima (fixed by the dataset: N=100000, E=1600000, F=H=128, OUT=40)
#define NMAX 100000
#define EMAX 1600000
#define FDIM 128
#define SCAN_BS 2048

// ---------------- scratch (static device globals; no allocation) ----------------
__device__ __align__(32) __half g_bufH[(size_t)NMAX * FDIM];  // h (fp16) — gather source
__device__ __align__(16) float  g_bufO[(size_t)NMAX * FDIM];  // out1, then s = out2+out1 (fp32)
__device__ __align__(32) __half g_W1h[FDIM * FDIM];           // W1 in fp16
__device__ __align__(32) __half g_W2h[FDIM * FDIM];           // W2 in fp16
__device__ float g_dinv[NMAX];
__device__ __align__(16) int g_cnt[NMAX + 8];
__device__ __align__(16) int g_rowstart[NMAX + 8];
__device__ __align__(16) int g_cursor[NMAX + 8];
__device__ int   g_csrc[EMAX];
__device__ int   g_bsum[64];
__device__ int   g_boff[64];

// ---------------- CSR build ----------------
__global__ void zero_cnt_kernel(int n) {
    int i = blockIdx.x * blockDim.x + threadIdx.x;
    if (i < n + 8) g_cnt[i] = 0;
}

__global__ void count_kernel(const int* __restrict__ dst, int e) {
    int i = blockIdx.x * blockDim.x + threadIdx.x;
    if (i < e) atomicAdd(&g_cnt[dst[i]], 1);
}

__global__ __launch_bounds__(256) void scan1_kernel(int n) {
    __shared__ int red[256];
    int b = blockIdx.x, t = threadIdx.x;
    int base = b * SCAN_BS + t * 8;
    int s = 0;
    if (base + 8 <= n) {
        int4 a = *(const int4*)&g_cnt[base];
        int4 c = *(const int4*)&g_cnt[base + 4];
        s = a.x + a.y + a.z + a.w + c.x + c.y + c.z + c.w;
    } else {
        for (int i = 0; i < 8; i++) {
            int idx = base + i;
            if (idx < n) s += g_cnt[idx];
        }
    }
    red[t] = s;
    __syncthreads();
    for (int off = 128; off > 0; off >>= 1) {
        if (t < off) red[t] += red[t + off];
        __syncthreads();
    }
    if (t == 0) g_bsum[b] = red[0];
}

__global__ void scan2_kernel(int nb, int n, int e_total) {
    if (threadIdx.x == 0 && blockIdx.x == 0) {
        int acc = 0;
        for (int i = 0; i < nb; i++) {
            g_boff[i] = acc;
            acc += g_bsum[i];
        }
        g_rowstart[n] = e_total;
    }
}

__global__ __launch_bounds__(256) void scan3_kernel(int n) {
    __shared__ int sh[256];
    int b = blockIdx.x, t = threadIdx.x;
    int base = b * SCAN_BS + t * 8;
    int loc[8];
    int s = 0;
    if (base + 8 <= n) {
        int4 a = *(const int4*)&g_cnt[base];
        int4 c = *(const int4*)&g_cnt[base + 4];
        loc[0] = a.x; loc[1] = a.y; loc[2] = a.z; loc[3] = a.w;
        loc[4] = c.x; loc[5] = c.y; loc[6] = c.z; loc[7] = c.w;
        s = a.x + a.y + a.z + a.w + c.x + c.y + c.z + c.w;
    } else {
#pragma unroll
        for (int i = 0; i < 8; i++) {
            int idx = base + i;
            loc[i] = (idx < n) ? g_cnt[idx] : 0;
            s += loc[i];
        }
    }
    sh[t] = s;
    __syncthreads();
    for (int off = 1; off < 256; off <<= 1) {
        int v = (t >= off) ? sh[t - off] : 0;
        __syncthreads();
        sh[t] += v;
        __syncthreads();
    }
    int pre = g_boff[b] + ((t > 0) ? sh[t - 1] : 0);
    if (base + 8 <= n) {
        int rs[8];
        float dv[8];
#pragma unroll
        for (int i = 0; i < 8; i++) {
            rs[i] = pre;
            dv[i] = rsqrtf((float)(loc[i] + 1));
            pre += loc[i];
        }
        *(int4*)&g_rowstart[base]     = make_int4(rs[0], rs[1], rs[2], rs[3]);
        *(int4*)&g_rowstart[base + 4] = make_int4(rs[4], rs[5], rs[6], rs[7]);
        *(int4*)&g_cursor[base]       = make_int4(rs[0], rs[1], rs[2], rs[3]);
        *(int4*)&g_cursor[base + 4]   = make_int4(rs[4], rs[5], rs[6], rs[7]);
        *(float4*)&g_dinv[base]       = make_float4(dv[0], dv[1], dv[2], dv[3]);
        *(float4*)&g_dinv[base + 4]   = make_float4(dv[4], dv[5], dv[6], dv[7]);
    } else {
#pragma unroll
        for (int i = 0; i < 8; i++) {
            int idx = base + i;
            if (idx < n) {
                g_rowstart[idx] = pre;
                g_cursor[idx]   = pre;
                g_dinv[idx]     = rsqrtf((float)(loc[i] + 1));
                pre += loc[i];
            }
        }
    }
}

__global__ void place_kernel(const int* __restrict__ src, const int* __restrict__ dst, int e) {
    int i = blockIdx.x * blockDim.x + threadIdx.x;
    if (i < e) {
        int d = dst[i];
        int p = atomicAdd(&g_cursor[d], 1);
        g_csrc[p] = src[i];
    }
}

// ---------------- W fp32 -> fp16 conversion (128x128 = 16384 elems) ----------------
__global__ void convert_w_kernel(const float* __restrict__ W, __half* __restrict__ Wh) {
    int i = (blockIdx.x * 256 + threadIdx.x) * 4;   // 4096 threads x 4
    if (i < FDIM * FDIM) {
        float4 v = *(const float4*)(W + i);
        __half2 h0 = __floats2half2_rn(v.x, v.y);
        __half2 h1 = __floats2half2_rn(v.z, v.w);
        *(uint2*)(Wh + i) = make_uint2(*(unsigned*)&h0, *(unsigned*)&h1);
    }
}

// ---------------- Tensor-core GEMM: H = fp16(A @ W);  A fp32 [n,128], Wh fp16 [128,128] ----
// Block: 128x128 tile, 256 threads = 8 warps (2x4), warp tile 64x32, WMMA m16n16k16 fp32-acc.
__global__ __launch_bounds__(256) void gemm_tc(const float* __restrict__ A,
                                               const __half* __restrict__ Wh,
                                               __half* __restrict__ H, int n) {
    __shared__ __half As[128][144];        // ld=144 halves (mult of 8) -> wmma-legal, 36.9 KB
    __shared__ float  St[8][16][20];       // ld=20 floats (mult of 4) -> wmma-legal, 10.2 KB
    int t = threadIdx.x;
    int wid = t >> 5, lane = t & 31;
    int m0 = blockIdx.x * 128;

    // stage A tile fp32 -> fp16 (coalesced float4 loads)
#pragma unroll
    for (int it = 0; it < 16; it++) {
        int flat = (it * 256 + t) * 4;     // covers 128*128
        int row = flat >> 7, col = flat & 127;
        float4 v = make_float4(0.f, 0.f, 0.f, 0.f);
        if (m0 + row < n)
            v = *(const float4*)(A + (size_t)(m0 + row) * 128 + col);
        __half2 h0 = __floats2half2_rn(v.x, v.y);
        __half2 h1 = __floats2half2_rn(v.z, v.w);
        *(uint2*)&As[row][col] = make_uint2(*(unsigned*)&h0, *(unsigned*)&h1);
    }
    __syncthreads();

    int warp_m = wid >> 2;   // 0..1 -> rows warp_m*64
    int warp_n = wid & 3;    // 0..3 -> cols warp_n*32

    wmma::fragment<wmma::accumulator, 16, 16, 16, float> c[4][2];
#pragma unroll
    for (int i = 0; i < 4; i++)
#pragma unroll
        for (int j = 0; j < 2; j++) wmma::fill_fragment(c[i][j], 0.0f);

#pragma unroll
    for (int kk = 0; kk < 128; kk += 16) {
        wmma::fragment<wmma::matrix_a, 16, 16, 16, __half, wmma::row_major> a[4];
        wmma::fragment<wmma::matrix_b, 16, 16, 16, __half, wmma::row_major> b[2];
#pragma unroll
        for (int i = 0; i < 4; i++)
            wmma::load_matrix_sync(a[i], &As[warp_m * 64 + i * 16][kk], 144);
#pragma unroll
        for (int j = 0; j < 2; j++)
            wmma::load_matrix_sync(b[j], Wh + (size_t)kk * 128 + warp_n * 32 + j * 16, 128);
#pragma unroll
        for (int i = 0; i < 4; i++)
#pragma unroll
            for (int j = 0; j < 2; j++)
                wmma::mma_sync(c[i][j], a[i], b[j], c[i][j]);
    }

    // epilogue: fragment -> smem stage (ld=20, legal) -> fp16 gmem
#pragma unroll
    for (int i = 0; i < 4; i++) {
#pragma unroll
        for (int j = 0; j < 2; j++) {
            wmma::store_matrix_sync(&St[wid][0][0], c[i][j], 20, wmma::mem_row_major);
            __syncwarp();
            int r = lane >> 1;              // 16 rows, 2 lanes/row
            int cbase = (lane & 1) * 8;     // 8 cols/lane
            int grow = m0 + warp_m * 64 + i * 16 + r;
            if (grow < n) {
                __half hbuf[8];
#pragma unroll
                for (int q = 0; q < 8; q++) hbuf[q] = __float2half_rn(St[wid][r][cbase + q]);
                *(uint4*)(H + (size_t)grow * 128 + warp_n * 32 + j * 16 + cbase) = *(uint4*)hbuf;
            }
            __syncwarp();
        }
    }
}

// ---------------- Aggregation: warp per node, fp16 gathers, fp32 accumulation ----------------
__global__ __launch_bounds__(256) void aggregate_kernel(const __half* __restrict__ H,
                                                        const float* __restrict__ bias,
                                                        float* O, const float* resid,
                                                        int has_resid, int n) {
    int warp = (blockIdx.x * blockDim.x + threadIdx.x) >> 5;
    int lane = threadIdx.x & 31;
    if (warp >= n) return;
    int s = g_rowstart[warp];
    int e = g_rowstart[warp + 1];
    const uint2* H8 = (const uint2*)H;
    size_t self = (size_t)warp * 32 + lane;
    float d = g_dinv[warp];

    uint2 raw = H8[self];
    float2 f0 = __half22float2(*(__half2*)&raw.x), f1 = __half22float2(*(__half2*)&raw.y);
    float4 acc = make_float4(f0.x * d, f0.y * d, f1.x * d, f1.y * d);

    int i = s;
    for (; i + 3 < e; i += 4) {
        int j0 = g_csrc[i];
        int j1 = g_csrc[i + 1];
        int j2 = g_csrc[i + 2];
        int j3 = g_csrc[i + 3];
        float d0 = g_dinv[j0], d1 = g_dinv[j1], d2 = g_dinv[j2], d3 = g_dinv[j3];
        uint2 r0 = H8[(size_t)j0 * 32 + lane];
        uint2 r1 = H8[(size_t)j1 * 32 + lane];
        uint2 r2 = H8[(size_t)j2 * 32 + lane];
        uint2 r3 = H8[(size_t)j3 * 32 + lane];
        {
            float2 a = __half22float2(*(__half2*)&r0.x), b = __half22float2(*(__half2*)&r0.y);
            acc.x = fmaf(a.x, d0, acc.x); acc.y = fmaf(a.y, d0, acc.y);
            acc.z = fmaf(b.x, d0, acc.z); acc.w = fmaf(b.y, d0, acc.w);
        }
        {
            float2 a = __half22float2(*(__half2*)&r1.x), b = __half22float2(*(__half2*)&r1.y);
            acc.x = fmaf(a.x, d1, acc.x); acc.y = fmaf(a.y, d1, acc.y);
            acc.z = fmaf(b.x, d1, acc.z); acc.w = fmaf(b.y, d1, acc.w);
        }
        {
            float2 a = __half22float2(*(__half2*)&r2.x), b = __half22float2(*(__half2*)&r2.y);
            acc.x = fmaf(a.x, d2, acc.x); acc.y = fmaf(a.y, d2, acc.y);
            acc.z = fmaf(b.x, d2, acc.z); acc.w = fmaf(b.y, d2, acc.w);
        }
        {
            float2 a = __half22float2(*(__half2*)&r3.x), b = __half22float2(*(__half2*)&r3.y);
            acc.x = fmaf(a.x, d3, acc.x); acc.y = fmaf(a.y, d3, acc.y);
            acc.z = fmaf(b.x, d3, acc.z); acc.w = fmaf(b.y, d3, acc.w);
        }
    }
    for (; i < e; i++) {
        int j = g_csrc[i];
        float dj = g_dinv[j];
        uint2 r = H8[(size_t)j * 32 + lane];
        float2 a = __half22float2(*(__half2*)&r.x), b = __half22float2(*(__half2*)&r.y);
        acc.x = fmaf(a.x, dj, acc.x); acc.y = fmaf(a.y, dj, acc.y);
        acc.z = fmaf(b.x, dj, acc.z); acc.w = fmaf(b.y, dj, acc.w);
    }

    float4 b = ((const float4*)bias)[lane];
    acc.x = fmaxf(fmaf(acc.x, d, b.x), 0.f);
    acc.y = fmaxf(fmaf(acc.y, d, b.y), 0.f);
    acc.z = fmaxf(fmaf(acc.z, d, b.z), 0.f);
    acc.w = fmaxf(fmaf(acc.w, d, b.w), 0.f);
    if (has_resid) {
        float4 r = ((const float4*)resid)[self];
        acc.x += r.x; acc.y += r.y; acc.z += r.z; acc.w += r.w;
    }
    ((float4*)O)[self] = acc;
}

// ---------------- Output GEMM: out = S @ Wc + bc;  S:[n,128] fp32, Wc:[128,40] ----------------
__global__ __launch_bounds__(256) void gemm_out_kernel(const float* __restrict__ S,
                                                       const float* __restrict__ Wc,
                                                       const float* __restrict__ bc,
                                                       float* __restrict__ out, int n) {
    __shared__ float Ws[128][40];
    __shared__ float Ss[128][33];
    __shared__ float bs[40];
    int t = threadIdx.x;
    int m0 = blockIdx.x * 128;
    for (int i = t; i < 128 * 40; i += 256) Ws[i / 40][i % 40] = Wc[i];
    if (t < 40) bs[t] = bc[t];

    int c0 = t & 7;
    int rq = t >> 3;
    float acc[4][5];
#pragma unroll
    for (int r = 0; r < 4; r++)
#pragma unroll
        for (int j = 0; j < 5; j++) acc[r][j] = 0.0f;

    for (int k0 = 0; k0 < 128; k0 += 32) {
        __syncthreads();
#pragma unroll
        for (int j = 0; j < 4; j++) {
            int flat = t * 16 + j * 4;
            int row = flat >> 5, kk = flat & 31;
            float4 v = make_float4(0.f, 0.f, 0.f, 0.f);
            if (m0 + row < n)
                v = *(const float4*)(S + (size_t)(m0 + row) * 128 + k0 + kk);
            Ss[row][kk + 0] = v.x;
            Ss[row][kk + 1] = v.y;
            Ss[row][kk + 2] = v.z;
            Ss[row][kk + 3] = v.w;
        }
        __syncthreads();
#pragma unroll 8
        for (int k = 0; k < 32; k++) {
            float w0 = Ws[k0 + k][c0];
            float w1 = Ws[k0 + k][c0 + 8];
            float w2 = Ws[k0 + k][c0 + 16];
            float w3 = Ws[k0 + k][c0 + 24];
            float w4 = Ws[k0 + k][c0 + 32];
#pragma unroll
            for (int r = 0; r < 4; r++) {
                float a = Ss[rq * 4 + r][k];
                acc[r][0] += a * w0;
                acc[r][1] += a * w1;
                acc[r][2] += a * w2;
                acc[r][3] += a * w3;
                acc[r][4] += a * w4;
            }
        }
    }
#pragma unroll
    for (int r = 0; r < 4; r++) {
        int row = m0 + rq * 4 + r;
        if (row < n) {
#pragma unroll
            for (int j = 0; j < 5; j++)
                out[(size_t)row * 40 + c0 + 8 * j] = acc[r][j] + bs[c0 + 8 * j];
        }
    }
}

// ---------------- launch (serial main chain; CSR forked under GEMM1) ----------------
extern "C" void kernel_launch(void* const* d_in, const int* in_sizes, int n_in,
                              void* d_out, int out_size) {
    const float* x  = (const float*)d_in[0];
    const float* W1 = (const float*)d_in[1];
    const float* b1 = (const float*)d_in[2];
    const float* W2 = (const float*)d_in[3];
    const float* b2 = (const float*)d_in[4];
    const float* Wc = (const float*)d_in[5];
    const float* bc = (const float*)d_in[6];
    const int*   ei = (const int*)d_in[7];

    int N = in_sizes[0] / FDIM;
    int E = in_sizes[7] / 2;
    if (N > NMAX) N = NMAX;
    if (E > EMAX) E = EMAX;
    const int* src = ei;
    const int* dst = ei + E;

    __half *H, *W1h, *W2h;
    float* O;
    cudaGetSymbolAddress((void**)&H,   g_bufH);
    cudaGetSymbolAddress((void**)&O,   g_bufO);
    cudaGetSymbolAddress((void**)&W1h, g_W1h);
    cudaGetSymbolAddress((void**)&W2h, g_W2h);

    static cudaStream_t s2 = nullptr;
    static cudaEvent_t ev_fork = nullptr, ev_csr = nullptr;
    if (s2 == nullptr) {
        cudaStreamCreateWithFlags(&s2, cudaStreamNonBlocking);
        cudaEventCreateWithFlags(&ev_fork, cudaEventDisableTiming);
        cudaEventCreateWithFlags(&ev_csr, cudaEventDisableTiming);
    }

    int nscanblk  = (N + SCAN_BS - 1) / SCAN_BS;
    int gemm_grid = (N + 127) / 128;
    int agg_grid  = (N * 32 + 255) / 256;

    // Fork: CSR build on s2, concurrent with W conversion + GEMM1 on stream 0.
    cudaEventRecord(ev_fork, 0);
    cudaStreamWaitEvent(s2, ev_fork, 0);
    zero_cnt_kernel<<<(N + 8 + 255) / 256, 256, 0, s2>>>(N);
    count_kernel<<<(E + 255) / 256, 256, 0, s2>>>(dst, E);
    scan1_kernel<<<nscanblk, 256, 0, s2>>>(N);
    scan2_kernel<<<1, 32, 0, s2>>>(nscanblk, N, E);
    scan3_kernel<<<nscanblk, 256, 0, s2>>>(N);
    place_kernel<<<(E + 255) / 256, 256, 0, s2>>>(src, dst, E);
    cudaEventRecord(ev_csr, s2);

    // Weight conversions (tiny) + Layer 1 GEMM on stream 0.
    convert_w_kernel<<<16, 256>>>(W1, W1h);
    convert_w_kernel<<<16, 256>>>(W2, W2h);
    gemm_tc<<<gemm_grid, 256>>>(x, W1h, H, N);

    // Join, then serial main chain.
    cudaStreamWaitEvent(0, ev_csr, 0);
    aggregate_kernel<<<agg_grid, 256>>>(H, b1, O, nullptr, 0, N);
    gemm_tc<<<gemm_grid, 256>>>(O, W2h, H, N);
    aggregate_kernel<<<agg_grid, 256>>>(H, b2, O, O, 1, N);
    gemm_out_kernel<<<gemm_grid, 256>>>(O, Wc, bc, (float*)d_out, N);
}

// round 16
// speedup vs baseline: 1.8567x; 1.1426x over previous
#include <cuda_runtime.h>
#include <cuda_fp16.h>
#include <mma.h>
#include <math.h>
#include <stdint.h>

using namespace nvcuda;

// Problem-size maxima (fixed by the dataset: N=100000, E=1600000, F=H=128, OUT=40)
#define NMAX 100000
#define EMAX 1600000
#define FDIM 128
#define SCAN_BS 2048
#define NPAD (NMAX + 128)   // pad rows so WMMA fragment loads past n stay in-bounds

// ---------------- scratch (static device globals; no allocation) ----------------
__device__ __align__(32) __half g_bufH [(size_t)NPAD * FDIM]; // h (fp16) — gather source
__device__ __align__(32) __half g_bufO1[(size_t)NPAD * FDIM]; // out1, then s (fp16, in-place)
__device__ __align__(32) __half g_W1h[FDIM * FDIM];           // W1 fp16
__device__ __align__(32) __half g_W2h[FDIM * FDIM];           // W2 fp16
__device__ __align__(32) __half g_Wch[FDIM * 48];             // Wc fp16, padded 40->48 cols
__device__ float g_dinv[NMAX];
__device__ __align__(16) int g_cnt[NMAX + 8];
__device__ __align__(16) int g_rowstart[NMAX + 8];
__device__ __align__(16) int g_cursor[NMAX + 8];
__device__ int   g_csrc[EMAX];
__device__ int   g_bsum[64];
__device__ int   g_boff[64];

// ---------------- CSR build ----------------
__global__ void zero_cnt_kernel(int n) {
    int i = blockIdx.x * blockDim.x + threadIdx.x;
    if (i < n + 8) g_cnt[i] = 0;
}

__global__ void count_kernel(const int* __restrict__ dst, int e) {
    int i = blockIdx.x * blockDim.x + threadIdx.x;
    if (i < e) atomicAdd(&g_cnt[dst[i]], 1);
}

__global__ __launch_bounds__(256) void scan1_kernel(int n) {
    __shared__ int red[256];
    int b = blockIdx.x, t = threadIdx.x;
    int base = b * SCAN_BS + t * 8;
    int s = 0;
    if (base + 8 <= n) {
        int4 a = *(const int4*)&g_cnt[base];
        int4 c = *(const int4*)&g_cnt[base + 4];
        s = a.x + a.y + a.z + a.w + c.x + c.y + c.z + c.w;
    } else {
        for (int i = 0; i < 8; i++) {
            int idx = base + i;
            if (idx < n) s += g_cnt[idx];
        }
    }
    red[t] = s;
    __syncthreads();
    for (int off = 128; off > 0; off >>= 1) {
        if (t < off) red[t] += red[t + off];
        __syncthreads();
    }
    if (t == 0) g_bsum[b] = red[0];
}

__global__ void scan2_kernel(int nb, int n, int e_total) {
    if (threadIdx.x == 0 && blockIdx.x == 0) {
        int acc = 0;
        for (int i = 0; i < nb; i++) {
            g_boff[i] = acc;
            acc += g_bsum[i];
        }
        g_rowstart[n] = e_total;
    }
}

__global__ __launch_bounds__(256) void scan3_kernel(int n) {
    __shared__ int sh[256];
    int b = blockIdx.x, t = threadIdx.x;
    int base = b * SCAN_BS + t * 8;
    int loc[8];
    int s = 0;
    if (base + 8 <= n) {
        int4 a = *(const int4*)&g_cnt[base];
        int4 c = *(const int4*)&g_cnt[base + 4];
        loc[0] = a.x; loc[1] = a.y; loc[2] = a.z; loc[3] = a.w;
        loc[4] = c.x; loc[5] = c.y; loc[6] = c.z; loc[7] = c.w;
        s = a.x + a.y + a.z + a.w + c.x + c.y + c.z + c.w;
    } else {
#pragma unroll
        for (int i = 0; i < 8; i++) {
            int idx = base + i;
            loc[i] = (idx < n) ? g_cnt[idx] : 0;
            s += loc[i];
        }
    }
    sh[t] = s;
    __syncthreads();
    for (int off = 1; off < 256; off <<= 1) {
        int v = (t >= off) ? sh[t - off] : 0;
        __syncthreads();
        sh[t] += v;
        __syncthreads();
    }
    int pre = g_boff[b] + ((t > 0) ? sh[t - 1] : 0);
    if (base + 8 <= n) {
        int rs[8];
        float dv[8];
#pragma unroll
        for (int i = 0; i < 8; i++) {
            rs[i] = pre;
            dv[i] = rsqrtf((float)(loc[i] + 1));
            pre += loc[i];
        }
        *(int4*)&g_rowstart[base]     = make_int4(rs[0], rs[1], rs[2], rs[3]);
        *(int4*)&g_rowstart[base + 4] = make_int4(rs[4], rs[5], rs[6], rs[7]);
        *(int4*)&g_cursor[base]       = make_int4(rs[0], rs[1], rs[2], rs[3]);
        *(int4*)&g_cursor[base + 4]   = make_int4(rs[4], rs[5], rs[6], rs[7]);
        *(float4*)&g_dinv[base]       = make_float4(dv[0], dv[1], dv[2], dv[3]);
        *(float4*)&g_dinv[base + 4]   = make_float4(dv[4], dv[5], dv[6], dv[7]);
    } else {
#pragma unroll
        for (int i = 0; i < 8; i++) {
            int idx = base + i;
            if (idx < n) {
                g_rowstart[idx] = pre;
                g_cursor[idx]   = pre;
                g_dinv[idx]     = rsqrtf((float)(loc[i] + 1));
                pre += loc[i];
            }
        }
    }
}

__global__ void place_kernel(const int* __restrict__ src, const int* __restrict__ dst, int e) {
    int i = blockIdx.x * blockDim.x + threadIdx.x;
    if (i < e) {
        int d = dst[i];
        int p = atomicAdd(&g_cursor[d], 1);
        g_csrc[p] = src[i];
    }
}

// ---------------- weight conversions ----------------
__global__ void convert_w_kernel(const float* __restrict__ W, __half* __restrict__ Wh) {
    int i = (blockIdx.x * 256 + threadIdx.x) * 4;
    if (i < FDIM * FDIM) {
        float4 v = *(const float4*)(W + i);
        __half2 h0 = __floats2half2_rn(v.x, v.y);
        __half2 h1 = __floats2half2_rn(v.z, v.w);
        *(uint2*)(Wh + i) = make_uint2(*(unsigned*)&h0, *(unsigned*)&h1);
    }
}

// Wc [128,40] fp32 -> [128,48] fp16 zero-padded
__global__ void convert_wc_kernel(const float* __restrict__ Wc, __half* __restrict__ Wch) {
    int i = blockIdx.x * 256 + threadIdx.x;   // over 128*48
    if (i < FDIM * 48) {
        int row = i / 48, col = i % 48;
        float v = (col < 40) ? Wc[row * 40 + col] : 0.0f;
        Wch[i] = __float2half_rn(v);
    }
}

// ---------------- TC GEMM (A fp32): H = fp16(A @ Wh) ----------------
__global__ __launch_bounds__(256) void gemm_tc_f32(const float* __restrict__ A,
                                                   const __half* __restrict__ Wh,
                                                   __half* __restrict__ H, int n) {
    __shared__ __align__(16) __half As[128][144];
    __shared__ __align__(16) float  St[8][16][20];
    int t = threadIdx.x;
    int wid = t >> 5, lane = t & 31;
    int m0 = blockIdx.x * 128;

#pragma unroll
    for (int it = 0; it < 16; it++) {
        int flat = (it * 256 + t) * 4;
        int row = flat >> 7, col = flat & 127;
        float4 v = make_float4(0.f, 0.f, 0.f, 0.f);
        if (m0 + row < n)
            v = *(const float4*)(A + (size_t)(m0 + row) * 128 + col);
        __half2 h0 = __floats2half2_rn(v.x, v.y);
        __half2 h1 = __floats2half2_rn(v.z, v.w);
        *(uint2*)&As[row][col] = make_uint2(*(unsigned*)&h0, *(unsigned*)&h1);
    }
    __syncthreads();

    int warp_m = wid >> 2;
    int warp_n = wid & 3;

    wmma::fragment<wmma::accumulator, 16, 16, 16, float> c[4][2];
#pragma unroll
    for (int i = 0; i < 4; i++)
#pragma unroll
        for (int j = 0; j < 2; j++) wmma::fill_fragment(c[i][j], 0.0f);

#pragma unroll
    for (int kk = 0; kk < 128; kk += 16) {
        wmma::fragment<wmma::matrix_a, 16, 16, 16, __half, wmma::row_major> a[4];
        wmma::fragment<wmma::matrix_b, 16, 16, 16, __half, wmma::row_major> b[2];
#pragma unroll
        for (int i = 0; i < 4; i++)
            wmma::load_matrix_sync(a[i], &As[warp_m * 64 + i * 16][kk], 144);
#pragma unroll
        for (int j = 0; j < 2; j++)
            wmma::load_matrix_sync(b[j], Wh + (size_t)kk * 128 + warp_n * 32 + j * 16, 128);
#pragma unroll
        for (int i = 0; i < 4; i++)
#pragma unroll
            for (int j = 0; j < 2; j++)
                wmma::mma_sync(c[i][j], a[i], b[j], c[i][j]);
    }

#pragma unroll
    for (int i = 0; i < 4; i++) {
#pragma unroll
        for (int j = 0; j < 2; j++) {
            wmma::store_matrix_sync(&St[wid][0][0], c[i][j], 20, wmma::mem_row_major);
            __syncwarp();
            int r = lane >> 1;
            int cbase = (lane & 1) * 8;
            int grow = m0 + warp_m * 64 + i * 16 + r;
            if (grow < n) {
                __half hbuf[8];
#pragma unroll
                for (int q = 0; q < 8; q++) hbuf[q] = __float2half_rn(St[wid][r][cbase + q]);
                *(uint4*)(H + (size_t)grow * 128 + warp_n * 32 + j * 16 + cbase) = *(uint4*)hbuf;
            }
            __syncwarp();
        }
    }
}

// ---------------- TC GEMM (A fp16): H = fp16(A @ Wh) ----------------
__global__ __launch_bounds__(256) void gemm_tc_f16(const __half* __restrict__ A,
                                                   const __half* __restrict__ Wh,
                                                   __half* __restrict__ H, int n) {
    __shared__ __align__(16) __half As[128][144];
    __shared__ __align__(16) float  St[8][16][20];
    int t = threadIdx.x;
    int wid = t >> 5, lane = t & 31;
    int m0 = blockIdx.x * 128;

#pragma unroll
    for (int it = 0; it < 8; it++) {
        int flat = (it * 256 + t) * 8;     // in halves
        int row = flat >> 7, col = flat & 127;
        uint4 v = make_uint4(0, 0, 0, 0);
        if (m0 + row < n)
            v = *(const uint4*)(A + (size_t)(m0 + row) * 128 + col);
        *(uint4*)&As[row][col] = v;
    }
    __syncthreads();

    int warp_m = wid >> 2;
    int warp_n = wid & 3;

    wmma::fragment<wmma::accumulator, 16, 16, 16, float> c[4][2];
#pragma unroll
    for (int i = 0; i < 4; i++)
#pragma unroll
        for (int j = 0; j < 2; j++) wmma::fill_fragment(c[i][j], 0.0f);

#pragma unroll
    for (int kk = 0; kk < 128; kk += 16) {
        wmma::fragment<wmma::matrix_a, 16, 16, 16, __half, wmma::row_major> a[4];
        wmma::fragment<wmma::matrix_b, 16, 16, 16, __half, wmma::row_major> b[2];
#pragma unroll
        for (int i = 0; i < 4; i++)
            wmma::load_matrix_sync(a[i], &As[warp_m * 64 + i * 16][kk], 144);
#pragma unroll
        for (int j = 0; j < 2; j++)
            wmma::load_matrix_sync(b[j], Wh + (size_t)kk * 128 + warp_n * 32 + j * 16, 128);
#pragma unroll
        for (int i = 0; i < 4; i++)
#pragma unroll
            for (int j = 0; j < 2; j++)
                wmma::mma_sync(c[i][j], a[i], b[j], c[i][j]);
    }

#pragma unroll
    for (int i = 0; i < 4; i++) {
#pragma unroll
        for (int j = 0; j < 2; j++) {
            wmma::store_matrix_sync(&St[wid][0][0], c[i][j], 20, wmma::mem_row_major);
            __syncwarp();
            int r = lane >> 1;
            int cbase = (lane & 1) * 8;
            int grow = m0 + warp_m * 64 + i * 16 + r;
            if (grow < n) {
                __half hbuf[8];
#pragma unroll
                for (int q = 0; q < 8; q++) hbuf[q] = __float2half_rn(St[wid][r][cbase + q]);
                *(uint4*)(H + (size_t)grow * 128 + warp_n * 32 + j * 16 + cbase) = *(uint4*)hbuf;
            }
            __syncwarp();
        }
    }
}

// ---------------- Aggregation: warp/node, fp16 gathers, fp32 acc, fp16 out ----------------
// O[i] = fp16( relu( dinv[i]*(sum_j h[j]*dinv[j] + h[i]*dinv[i]) + bias ) [+ resid[i]] )
__global__ __launch_bounds__(256) void aggregate_kernel(const __half* __restrict__ H,
                                                        const float* __restrict__ bias,
                                                        __half* O, const __half* resid,
                                                        int has_resid, int n) {
    int warp = (blockIdx.x * blockDim.x + threadIdx.x) >> 5;
    int lane = threadIdx.x & 31;
    if (warp >= n) return;
    int s = g_rowstart[warp];
    int e = g_rowstart[warp + 1];
    const uint2* H8 = (const uint2*)H;
    size_t self = (size_t)warp * 32 + lane;
    float d = g_dinv[warp];

    uint2 raw = H8[self];
    float2 f0 = __half22float2(*(__half2*)&raw.x), f1 = __half22float2(*(__half2*)&raw.y);
    float4 acc = make_float4(f0.x * d, f0.y * d, f1.x * d, f1.y * d);

    int i = s;
    for (; i + 3 < e; i += 4) {
        int j0 = g_csrc[i];
        int j1 = g_csrc[i + 1];
        int j2 = g_csrc[i + 2];
        int j3 = g_csrc[i + 3];
        float d0 = g_dinv[j0], d1 = g_dinv[j1], d2 = g_dinv[j2], d3 = g_dinv[j3];
        uint2 r0 = H8[(size_t)j0 * 32 + lane];
        uint2 r1 = H8[(size_t)j1 * 32 + lane];
        uint2 r2 = H8[(size_t)j2 * 32 + lane];
        uint2 r3 = H8[(size_t)j3 * 32 + lane];
        {
            float2 a = __half22float2(*(__half2*)&r0.x), b = __half22float2(*(__half2*)&r0.y);
            acc.x = fmaf(a.x, d0, acc.x); acc.y = fmaf(a.y, d0, acc.y);
            acc.z = fmaf(b.x, d0, acc.z); acc.w = fmaf(b.y, d0, acc.w);
        }
        {
            float2 a = __half22float2(*(__half2*)&r1.x), b = __half22float2(*(__half2*)&r1.y);
            acc.x = fmaf(a.x, d1, acc.x); acc.y = fmaf(a.y, d1, acc.y);
            acc.z = fmaf(b.x, d1, acc.z); acc.w = fmaf(b.y, d1, acc.w);
        }
        {
            float2 a = __half22float2(*(__half2*)&r2.x), b = __half22float2(*(__half2*)&r2.y);
            acc.x = fmaf(a.x, d2, acc.x); acc.y = fmaf(a.y, d2, acc.y);
            acc.z = fmaf(b.x, d2, acc.z); acc.w = fmaf(b.y, d2, acc.w);
        }
        {
            float2 a = __half22float2(*(__half2*)&r3.x), b = __half22float2(*(__half2*)&r3.y);
            acc.x = fmaf(a.x, d3, acc.x); acc.y = fmaf(a.y, d3, acc.y);
            acc.z = fmaf(b.x, d3, acc.z); acc.w = fmaf(b.y, d3, acc.w);
        }
    }
    for (; i < e; i++) {
        int j = g_csrc[i];
        float dj = g_dinv[j];
        uint2 r = H8[(size_t)j * 32 + lane];
        float2 a = __half22float2(*(__half2*)&r.x), b = __half22float2(*(__half2*)&r.y);
        acc.x = fmaf(a.x, dj, acc.x); acc.y = fmaf(a.y, dj, acc.y);
        acc.z = fmaf(b.x, dj, acc.z); acc.w = fmaf(b.y, dj, acc.w);
    }

    float4 b = ((const float4*)bias)[lane];
    acc.x = fmaxf(fmaf(acc.x, d, b.x), 0.f);
    acc.y = fmaxf(fmaf(acc.y, d, b.y), 0.f);
    acc.z = fmaxf(fmaf(acc.z, d, b.z), 0.f);
    acc.w = fmaxf(fmaf(acc.w, d, b.w), 0.f);
    if (has_resid) {
        uint2 rr = ((const uint2*)resid)[self];
        float2 a = __half22float2(*(__half2*)&rr.x), c = __half22float2(*(__half2*)&rr.y);
        acc.x += a.x; acc.y += a.y; acc.z += c.x; acc.w += c.y;
    }
    __half2 o0 = __floats2half2_rn(acc.x, acc.y);
    __half2 o1 = __floats2half2_rn(acc.z, acc.w);
    ((uint2*)O)[self] = make_uint2(*(unsigned*)&o0, *(unsigned*)&o1);
}

// ---------------- Output GEMM (TC): out = S @ Wch + bc;  S fp16 [n,128], Wch fp16 [128,48] ----
// Block: 128 rows, 8 warps, warp = 16 rows x 48 cols (3 n-fragments). fp32 out [n,40].
__global__ __launch_bounds__(256) void gemm_out_tc(const __half* __restrict__ S,
                                                   const __half* __restrict__ Wch,
                                                   const float* __restrict__ bc,
                                                   float* __restrict__ out, int n) {
    __shared__ __align__(16) float St[8][16][48];
    __shared__ float bs[48];
    int t = threadIdx.x;
    int w = t >> 5, lane = t & 31;
    if (t < 48) bs[t] = (t < 40) ? bc[t] : 0.0f;
    __syncthreads();

    int row0 = blockIdx.x * 128 + w * 16;   // fragment rows stay in padded buffer (NPAD)

    wmma::fragment<wmma::accumulator, 16, 16, 16, float> c[3];
#pragma unroll
    for (int j = 0; j < 3; j++) wmma::fill_fragment(c[j], 0.0f);

#pragma unroll
    for (int kk = 0; kk < 128; kk += 16) {
        wmma::fragment<wmma::matrix_a, 16, 16, 16, __half, wmma::row_major> a;
        wmma::load_matrix_sync(a, S + (size_t)row0 * 128 + kk, 128);
        wmma::fragment<wmma::matrix_b, 16, 16, 16, __half, wmma::row_major> b[3];
#pragma unroll
        for (int j = 0; j < 3; j++)
            wmma::load_matrix_sync(b[j], Wch + (size_t)kk * 48 + j * 16, 48);
#pragma unroll
        for (int j = 0; j < 3; j++)
            wmma::mma_sync(c[j], a, b[j], c[j]);
    }

#pragma unroll
    for (int j = 0; j < 3; j++)
        wmma::store_matrix_sync(&St[w][0][j * 16], c[j], 48, wmma::mem_row_major);
    __syncwarp();

    int r = lane >> 1;                 // 16 rows, 2 lanes/row
    int cb = (lane & 1) * 20;          // 20 cols per lane
    int grow = row0 + r;
    if (grow < n) {
#pragma unroll
        for (int q = 0; q < 5; q++) {
            float4 v;
            v.x = St[w][r][cb + q * 4 + 0] + bs[cb + q * 4 + 0];
            v.y = St[w][r][cb + q * 4 + 1] + bs[cb + q * 4 + 1];
            v.z = St[w][r][cb + q * 4 + 2] + bs[cb + q * 4 + 2];
            v.w = St[w][r][cb + q * 4 + 3] + bs[cb + q * 4 + 3];
            *(float4*)(out + (size_t)grow * 40 + cb + q * 4) = v;
        }
    }
}

// ---------------- launch (serial main chain; CSR forked under GEMM1) ----------------
extern "C" void kernel_launch(void* const* d_in, const int* in_sizes, int n_in,
                              void* d_out, int out_size) {
    const float* x  = (const float*)d_in[0];
    const float* W1 = (const float*)d_in[1];
    const float* b1 = (const float*)d_in[2];
    const float* W2 = (const float*)d_in[3];
    const float* b2 = (const float*)d_in[4];
    const float* Wc = (const float*)d_in[5];
    const float* bc = (const float*)d_in[6];
    const int*   ei = (const int*)d_in[7];

    int N = in_sizes[0] / FDIM;
    int E = in_sizes[7] / 2;
    if (N > NMAX) N = NMAX;
    if (E > EMAX) E = EMAX;
    const int* src = ei;
    const int* dst = ei + E;

    __half *H, *O1, *W1h, *W2h, *Wch;
    cudaGetSymbolAddress((void**)&H,   g_bufH);
    cudaGetSymbolAddress((void**)&O1,  g_bufO1);
    cudaGetSymbolAddress((void**)&W1h, g_W1h);
    cudaGetSymbolAddress((void**)&W2h, g_W2h);
    cudaGetSymbolAddress((void**)&Wch, g_Wch);

    static cudaStream_t s2 = nullptr;
    static cudaEvent_t ev_fork = nullptr, ev_csr = nullptr;
    if (s2 == nullptr) {
        cudaStreamCreateWithFlags(&s2, cudaStreamNonBlocking);
        cudaEventCreateWithFlags(&ev_fork, cudaEventDisableTiming);
        cudaEventCreateWithFlags(&ev_csr, cudaEventDisableTiming);
    }

    int nscanblk  = (N + SCAN_BS - 1) / SCAN_BS;
    int gemm_grid = (N + 127) / 128;
    int agg_grid  = (N * 32 + 255) / 256;

    // Fork: CSR build on s2, concurrent with W conversion + GEMM1 on stream 0.
    cudaEventRecord(ev_fork, 0);
    cudaStreamWaitEvent(s2, ev_fork, 0);
    zero_cnt_kernel<<<(N + 8 + 255) / 256, 256, 0, s2>>>(N);
    count_kernel<<<(E + 255) / 256, 256, 0, s2>>>(dst, E);
    scan1_kernel<<<nscanblk, 256, 0, s2>>>(N);
    scan2_kernel<<<1, 32, 0, s2>>>(nscanblk, N, E);
    scan3_kernel<<<nscanblk, 256, 0, s2>>>(N);
    place_kernel<<<(E + 255) / 256, 256, 0, s2>>>(src, dst, E);
    cudaEventRecord(ev_csr, s2);

    // Weight conversions + Layer 1 GEMM on stream 0.
    convert_w_kernel<<<16, 256>>>(W1, W1h);
    convert_w_kernel<<<16, 256>>>(W2, W2h);
    convert_wc_kernel<<<24, 256>>>(Wc, Wch);
    gemm_tc_f32<<<gemm_grid, 256>>>(x, W1h, H, N);

    // Join, then serial main chain (all intermediates fp16).
    cudaStreamWaitEvent(0, ev_csr, 0);
    aggregate_kernel<<<agg_grid, 256>>>(H, b1, O1, nullptr, 0, N);   // out1 (fp16)
    gemm_tc_f16<<<gemm_grid, 256>>>(O1, W2h, H, N);                  // h2 (fp16)
    aggregate_kernel<<<agg_grid, 256>>>(H, b2, O1, O1, 1, N);        // s = out2+out1 (in-place fp16)
    gemm_out_tc<<<gemm_grid, 256>>>(O1, Wch, bc, (float*)d_out, N);  // out fp32
}